// round 9
// baseline (speedup 1.0000x reference)
#include <cuda_runtime.h>
#include <cuda_bf16.h>
#include <stdint.h>

#define TPB   256
#define NNODE 49
#define BT    2
#define BMAX  4096
#define DIM   768
#define C1    256
#define C2    128
#define NCLS  13
#define NST1  24           // 768/32 K32 stages
#define NST2  8            // 256/32

#define SROW 80            // stage tile row stride bytes (32 bf16 data + pad) -> conflict-free LDSM
#define SH   264           // H1 row stride (bf16 elems) = 528B
#define DS   65            // d1s fp32 row stride

// ---- GEMM1 stage layout (bytes within stage) ----
#define A_HI 0             // 128 x 80
#define A_LO 10240
#define B_HI 20480         // 256 x 80
#define B_LO 40960
#define STG  61440         // x3 stages: [0, 184320)
// ---- phase-2 layout (aliases stage region; GEMM1 retired first) ----
#define OFF_H1HI 0         // 128 x 264 bf16 = 67584
#define OFF_H1LO 67584
#define OFF_D1S  135168    // 128 x 65 fp32 = 33280
#define OFF_B2   168448    // 2 stages x 20480 (hi 10240 | lo 10240) -> [168448, 209408)
#define B2_STG   20480
// ---- persistent misc ----
#define OFF_ADJW 209408
#define OFF_ADJI 211200
#define OFF_DINV 212992
#define OFF_POOL 213248
#define SMEM_BYTES 214528

// ---- pre-split operands (filled by prep kernels) ----
__device__ __nv_bfloat16 g_xh[(size_t)BMAX * NNODE * DIM];
__device__ __nv_bfloat16 g_xl[(size_t)BMAX * NNODE * DIM];
__device__ __nv_bfloat16 g_W1hi[C1 * DIM];
__device__ __nv_bfloat16 g_W1lo[C1 * DIM];
__device__ __nv_bfloat16 g_W2hi[C2 * C1];
__device__ __nv_bfloat16 g_W2lo[C2 * C1];

__device__ __forceinline__ void mma_bf16(float* c, const unsigned* a, const unsigned* b) {
    asm volatile(
        "mma.sync.aligned.m16n8k16.row.col.f32.bf16.bf16.f32 "
        "{%0,%1,%2,%3}, {%4,%5,%6,%7}, {%8,%9}, {%0,%1,%2,%3};\n"
        : "+f"(c[0]), "+f"(c[1]), "+f"(c[2]), "+f"(c[3])
        : "r"(a[0]), "r"(a[1]), "r"(a[2]), "r"(a[3]), "r"(b[0]), "r"(b[1]));
}
__device__ __forceinline__ void ldsm4(unsigned* r, uint32_t addr) {
    asm volatile("ldmatrix.sync.aligned.m8n8.x4.shared.b16 {%0,%1,%2,%3}, [%4];"
        : "=r"(r[0]), "=r"(r[1]), "=r"(r[2]), "=r"(r[3]) : "r"(addr));
}
__device__ __forceinline__ void cpa16(uint32_t dst, const void* src) {
    asm volatile("cp.async.cg.shared.global [%0], [%1], 16;" :: "r"(dst), "l"(src));
}
__device__ __forceinline__ void cpa16z(uint32_t dst, const void* src, int srcsize) {
    asm volatile("cp.async.cg.shared.global [%0], [%1], 16, %2;"
                 :: "r"(dst), "l"(src), "r"(srcsize));
}
#define CPA_COMMIT() asm volatile("cp.async.commit_group;" ::: "memory")
#define CPA_WAIT0()  asm volatile("cp.async.wait_group 0;" ::: "memory")
#define CPA_WAIT1()  asm volatile("cp.async.wait_group 1;" ::: "memory")

__device__ __forceinline__ unsigned packbf(__nv_bfloat16 a, __nv_bfloat16 b) {
    return ((unsigned)__bfloat16_as_ushort(b) << 16) | (unsigned)__bfloat16_as_ushort(a);
}

// ==================== prep: split x into bf16 hi/lo ====================
__global__ void prep_x(const float4* __restrict__ x4, int n4) {
    int i = blockIdx.x * blockDim.x + threadIdx.x;
    if (i >= n4) return;
    float4 v = x4[i];
    __nv_bfloat16 h0 = __float2bfloat16(v.x), h1 = __float2bfloat16(v.y);
    __nv_bfloat16 h2 = __float2bfloat16(v.z), h3 = __float2bfloat16(v.w);
    __nv_bfloat16 l0 = __float2bfloat16(v.x - __bfloat162float(h0));
    __nv_bfloat16 l1 = __float2bfloat16(v.y - __bfloat162float(h1));
    __nv_bfloat16 l2 = __float2bfloat16(v.z - __bfloat162float(h2));
    __nv_bfloat16 l3 = __float2bfloat16(v.w - __bfloat162float(h3));
    *(uint2*)(g_xh + (size_t)i * 4) = make_uint2(packbf(h0, h1), packbf(h2, h3));
    *(uint2*)(g_xl + (size_t)i * 4) = make_uint2(packbf(l0, l1), packbf(l2, l3));
}

// ==================== prep: split + transpose weights ====================
__global__ void prep_weights(const float* __restrict__ W1, const float* __restrict__ W2) {
    int idx = blockIdx.x * blockDim.x + threadIdx.x;
    if (idx < C1 * DIM) {                       // W1 [768][256] -> [256][768]
        int k = idx >> 8, n = idx & 255;
        float v = W1[idx];
        __nv_bfloat16 h = __float2bfloat16(v);
        g_W1hi[n * DIM + k] = h;
        g_W1lo[n * DIM + k] = __float2bfloat16(v - __bfloat162float(h));
    } else if (idx < C1 * DIM + C1 * C2) {      // W2 [256][128] -> [128][256]
        int j = idx - C1 * DIM;
        int k = j >> 7, n = j & 127;
        float v = W2[j];
        __nv_bfloat16 h = __float2bfloat16(v);
        g_W2hi[n * C1 + k] = h;
        g_W2lo[n * C1 + k] = __float2bfloat16(v - __bfloat162float(h));
    }
}

// =========================== main fused kernel ===========================
__global__ void __launch_bounds__(TPB, 1)
gnn_fused(const float* __restrict__ b1, const float* __restrict__ b2,
          const float* __restrict__ Wf, const float* __restrict__ bf,
          float* __restrict__ out)
{
    extern __shared__ unsigned char smem[];
    const uint32_t sbase = (uint32_t)__cvta_generic_to_shared(smem);

    float* adjw   = (float*)(smem + OFF_ADJW);
    int*   adji   = (int*)(smem + OFF_ADJI);
    float* dinv   = (float*)(smem + OFF_DINV);
    float* pooled = (float*)(smem + OFF_POOL);
    float* d1s    = (float*)(smem + OFF_D1S);

    const int tid  = threadIdx.x;
    const int lane = tid & 31;
    const int wid  = tid >> 5;    // 0..7
    const int wm   = wid >> 2;    // 0..1  (m64 block)
    const int wn   = wid & 3;     // 0..3  (n64 G1 / n32 G2)
    const int tr   = lane >> 2;
    const int tc   = lane & 3;
    const int b0   = blockIdx.x * BT;

    // ldmatrix lane pattern
    const int lrow = (lane & 7) + ((lane >> 3) & 1) * 8;
    const int lkb  = (lane >> 4) * 16;

    // ---- adjacency (exact fp32) ----
    if (tid < NNODE) {
        int r = tid / 7, c = tid % 7;
        int nr = min(r + 1, 6) - max(r - 1, 0) + 1;
        int nc = min(c + 1, 6) - max(c - 1, 0) + 1;
        dinv[tid] = 1.0f / sqrtf((float)(nr * nc));
    }
    __syncthreads();
    if (tid < NNODE) {
        int r = tid / 7, c = tid % 7;
        float di = dinv[tid];
        int t = 0;
        for (int dr = -1; dr <= 1; dr++)
            for (int dc = -1; dc <= 1; dc++) {
                int rr = r + dr, cc = c + dc;
                if (rr >= 0 && rr < 7 && cc >= 0 && cc < 7) {
                    int j = rr * 7 + cc;
                    adji[tid * 9 + t] = j;
                    adjw[tid * 9 + t] = di * dinv[j];
                    t++;
                }
            }
        for (; t < 9; t++) { adji[tid * 9 + t] = 0; adjw[tid * 9 + t] = 0.0f; }
    }

    // ---- staging thread assignments ----
    // A: row = tid>>1 (0..127), chunks c = (tid&1)*2 + {0,1}
    const int arow  = tid >> 1;
    const int ac0   = (tid & 1) * 2;
    const int ag    = arow >> 6;
    const int anode = arow & 63;
    const int asz   = (anode < NNODE) ? 16 : 0;
    const int anc   = min(anode, NNODE - 1);
    const __nv_bfloat16* pxh = g_xh + ((size_t)(b0 + ag) * NNODE + anc) * DIM;
    const __nv_bfloat16* pxl = g_xl + ((size_t)(b0 + ag) * NNODE + anc) * DIM;
    const uint32_t adst = (uint32_t)(arow * SROW + ac0 * 16);
    // B: n = tid, chunks 0..3
    const __nv_bfloat16* pw1h = g_W1hi + (size_t)tid * DIM;
    const __nv_bfloat16* pw1l = g_W1lo + (size_t)tid * DIM;
    const uint32_t bdst = (uint32_t)(tid * SROW);

    // frag base byte offsets
    const uint32_t aoff = (uint32_t)((wm * 64 + lrow) * SROW + lkb);
    const uint32_t boff = (uint32_t)((wn * 64 + lrow) * SROW + lkb);

    // ---- GEMM1 stage filler ----
    auto fill1 = [&](int kt, uint32_t stg) {
        const int ke = kt * 32;
        #pragma unroll
        for (int c = 0; c < 2; c++) {
            cpa16z(sbase + stg + A_HI + adst + c * 16, pxh + ke + (ac0 + c) * 8, asz);
            cpa16z(sbase + stg + A_LO + adst + c * 16, pxl + ke + (ac0 + c) * 8, asz);
        }
        #pragma unroll
        for (int c = 0; c < 4; c++) {
            cpa16(sbase + stg + B_HI + bdst + c * 16, pw1h + ke + c * 8);
            cpa16(sbase + stg + B_LO + bdst + c * 16, pw1l + ke + c * 8);
        }
        CPA_COMMIT();
    };

    // =========== GEMM1: T1 = X @ W1  (128 x 256 x 768, bf16x3) ===========
    float acc[32][4];
    #pragma unroll
    for (int j = 0; j < 32; j++)
        #pragma unroll
        for (int k = 0; k < 4; k++) acc[j][k] = 0.0f;

    fill1(0, 0);
    fill1(1, STG);

    #pragma unroll 1
    for (int kt = 0; kt < NST1; kt++) {
        const uint32_t cs = (uint32_t)(kt % 3) * STG;
        if (kt < NST1 - 2) CPA_WAIT1(); else CPA_WAIT0();
        __syncthreads();
        if (kt + 2 < NST1) fill1(kt + 2, (uint32_t)((kt + 2) % 3) * STG);

        #pragma unroll
        for (int kh = 0; kh < 2; kh++) {
            unsigned afh[4][4], afl[4][4];
            #pragma unroll
            for (int mi = 0; mi < 4; mi++) {
                ldsm4(afh[mi], sbase + cs + A_HI + aoff + mi * 16 * SROW + kh * 32);
                ldsm4(afl[mi], sbase + cs + A_LO + aoff + mi * 16 * SROW + kh * 32);
            }
            #pragma unroll
            for (int p = 0; p < 4; p++) {
                unsigned bh4[4], bl4[4];
                ldsm4(bh4, sbase + cs + B_HI + boff + p * 16 * SROW + kh * 32);
                ldsm4(bl4, sbase + cs + B_LO + boff + p * 16 * SROW + kh * 32);
                #pragma unroll
                for (int h = 0; h < 2; h++) {
                    const int nj = p * 2 + h;
                    unsigned bh[2] = { bh4[h], bh4[2 + h] };
                    unsigned bl[2] = { bl4[h], bl4[2 + h] };
                    #pragma unroll
                    for (int mi = 0; mi < 4; mi++) {
                        mma_bf16(acc[mi*8+nj], afh[mi], bh);
                        mma_bf16(acc[mi*8+nj], afh[mi], bl);
                        mma_bf16(acc[mi*8+nj], afl[mi], bh);
                    }
                }
            }
        }
    }
    __syncthreads();

    // prefetch GEMM2 B stage 0 early (latency absorbed by epilogue 1)
    const int b2n = tid & 127;
    const int b2c = (tid >> 7) * 2;
    const __nv_bfloat16* pw2h = g_W2hi + (size_t)b2n * C1;
    const __nv_bfloat16* pw2l = g_W2lo + (size_t)b2n * C1;
    const uint32_t b2dst = (uint32_t)(b2n * SROW + b2c * 16);
    auto fill2 = [&](int kt, uint32_t stg) {
        const int ke = kt * 32;
        #pragma unroll
        for (int c = 0; c < 2; c++) {
            cpa16(sbase + stg + b2dst + c * 16,         pw2h + ke + (b2c + c) * 8);
            cpa16(sbase + stg + 10240 + b2dst + c * 16, pw2l + ke + (b2c + c) * 8);
        }
        CPA_COMMIT();
    };
    fill2(0, OFF_B2);

    // ===== epilogue 1: H1 = relu(ADJ @ T1 + b1), split bf16 hi/lo =====
    __nv_bfloat16* H1hi = (__nv_bfloat16*)(smem + OFF_H1HI);
    __nv_bfloat16* H1lo = (__nv_bfloat16*)(smem + OFF_H1LO);
    #pragma unroll 1
    for (int ci = 0; ci < 4; ci++) {
        if (wn == ci) {
            #pragma unroll
            for (int mi = 0; mi < 4; mi++)
                #pragma unroll
                for (int nj = 0; nj < 8; nj++) {
                    const int row = wm*64 + mi*16 + tr;
                    const int col = nj*8 + tc*2;
                    float* a = acc[mi*8+nj];
                    d1s[row * DS + col]           = a[0];
                    d1s[row * DS + col + 1]       = a[1];
                    d1s[(row + 8) * DS + col]     = a[2];
                    d1s[(row + 8) * DS + col + 1] = a[3];
                }
        }
        __syncthreads();
        for (int task = tid; task < BT * NNODE * 64; task += TPB) {
            const int cl   = task & 63;
            const int rest = task >> 6;
            const int g    = (rest >= NNODE) ? 1 : 0;
            const int i    = rest - g * NNODE;
            float s = __ldg(&b1[ci * 64 + cl]);
            #pragma unroll
            for (int t = 0; t < 9; t++)
                s += adjw[i*9+t] * d1s[(g*64 + adji[i*9+t]) * DS + cl];
            s = fmaxf(s, 0.0f);
            __nv_bfloat16 h = __float2bfloat16(s);
            H1hi[(g*64 + i) * SH + ci*64 + cl] = h;
            H1lo[(g*64 + i) * SH + ci*64 + cl] = __float2bfloat16(s - __bfloat162float(h));
        }
        __syncthreads();
    }

    // =========== GEMM2: T2 = H1 @ W2  (128 x 128 x 256, bf16x3) ===========
    float acc2[16][4];
    #pragma unroll
    for (int j = 0; j < 16; j++)
        #pragma unroll
        for (int k = 0; k < 4; k++) acc2[j][k] = 0.0f;

    const uint32_t hoff  = (uint32_t)((wm * 64 + lrow) * (SH * 2) + lkb);
    const uint32_t b2off = (uint32_t)((wn * 32 + lrow) * SROW + lkb);

    #pragma unroll 1
    for (int kt = 0; kt < NST2; kt++) {
        const uint32_t cs = OFF_B2 + (uint32_t)(kt & 1) * B2_STG;
        CPA_WAIT0();
        __syncthreads();
        if (kt + 1 < NST2) fill2(kt + 1, OFF_B2 + (uint32_t)((kt + 1) & 1) * B2_STG);

        #pragma unroll
        for (int kh = 0; kh < 2; kh++) {
            unsigned afh[4][4], afl[4][4];
            #pragma unroll
            for (int mi = 0; mi < 4; mi++) {
                ldsm4(afh[mi], sbase + OFF_H1HI + hoff + mi*16*(SH*2) + kt*64 + kh*32);
                ldsm4(afl[mi], sbase + OFF_H1LO + hoff + mi*16*(SH*2) + kt*64 + kh*32);
            }
            #pragma unroll
            for (int p = 0; p < 2; p++) {
                unsigned bh4[4], bl4[4];
                ldsm4(bh4, sbase + cs + b2off + p*16*SROW + kh*32);
                ldsm4(bl4, sbase + cs + 10240 + b2off + p*16*SROW + kh*32);
                #pragma unroll
                for (int h = 0; h < 2; h++) {
                    const int nj = p*2 + h;
                    unsigned bh[2] = { bh4[h], bh4[2+h] };
                    unsigned bl[2] = { bl4[h], bl4[2+h] };
                    #pragma unroll
                    for (int mi = 0; mi < 4; mi++) {
                        mma_bf16(acc2[mi*4+nj], afh[mi], bh);
                        mma_bf16(acc2[mi*4+nj], afh[mi], bl);
                        mma_bf16(acc2[mi*4+nj], afl[mi], bh);
                    }
                }
            }
        }
    }
    __syncthreads();

    // ======== epilogue 2: ADJ + bias + relu + mean-pool + head ========
    #pragma unroll 1
    for (int ci = 0; ci < 2; ci++) {
        if ((wn >> 1) == ci) {
            #pragma unroll
            for (int mi = 0; mi < 4; mi++)
                #pragma unroll
                for (int nj = 0; nj < 4; nj++) {
                    const int row = wm*64 + mi*16 + tr;
                    const int col = (wn & 1)*32 + nj*8 + tc*2;
                    float* a = acc2[mi*4+nj];
                    d1s[row * DS + col]           = a[0];
                    d1s[row * DS + col + 1]       = a[1];
                    d1s[(row + 8) * DS + col]     = a[2];
                    d1s[(row + 8) * DS + col + 1] = a[3];
                }
        }
        __syncthreads();
        {
            const int half = tid & 1;
            const int rest = tid >> 1;          // 0..127
            const int g    = rest >> 6;
            const int cl   = rest & 63;
            const float bias = __ldg(&b2[ci * 64 + cl]);
            const int i0   = half * 25;
            const int icnt = half ? 24 : 25;
            float ps = 0.0f;
            for (int ii = 0; ii < icnt; ii++) {
                const int i = i0 + ii;
                float s = bias;
                #pragma unroll
                for (int t = 0; t < 9; t++)
                    s += adjw[i*9+t] * d1s[(g*64 + adji[i*9+t]) * DS + cl];
                ps += fmaxf(s, 0.0f);
            }
            ps += __shfl_xor_sync(0xFFFFFFFFu, ps, 1);
            if (half == 0) pooled[g * C2 + ci * 64 + cl] = ps * (1.0f / 49.0f);
        }
        __syncthreads();
    }

    if (tid < BT * NCLS) {
        const int g = tid / NCLS, o = tid - g * NCLS;
        float s = __ldg(&bf[o]);
        const float* pp = pooled + g * C2;
        #pragma unroll 8
        for (int k = 0; k < C2; k++) s += pp[k] * __ldg(&Wf[k * NCLS + o]);
        out[(size_t)(b0 + g) * NCLS + o] = s;
    }
}

extern "C" void kernel_launch(void* const* d_in, const int* in_sizes, int n_in,
                              void* d_out, int out_size)
{
    const float* x  = (const float*)d_in[0];
    const float* W1 = (const float*)d_in[1];
    const float* b1 = (const float*)d_in[2];
    const float* W2 = (const float*)d_in[3];
    const float* b2 = (const float*)d_in[4];
    const float* Wf = (const float*)d_in[5];
    const float* bf = (const float*)d_in[6];
    float* out = (float*)d_out;

    const int B  = in_sizes[0] / (NNODE * DIM);   // 4096
    const int n4 = in_sizes[0] / 4;

    prep_x<<<(n4 + 255) / 256, 256>>>((const float4*)x, n4);
    prep_weights<<<(C1 * DIM + C1 * C2 + 255) / 256, 256>>>(W1, W2);

    cudaFuncSetAttribute(gnn_fused, cudaFuncAttributeMaxDynamicSharedMemorySize, SMEM_BYTES);
    gnn_fused<<<B / BT, TPB, SMEM_BYTES>>>(b1, b2, Wf, bf, out);
}

// round 11
// speedup vs baseline: 1.0267x; 1.0267x over previous
#include <cuda_runtime.h>
#include <cuda_bf16.h>
#include <stdint.h>

#define TPB   512
#define NNODE 49
#define BT    2
#define BMAX  4096
#define DIM   768
#define C1    256
#define C2    128
#define NCLS  13
#define NST1  24           // 768/32 K32 stages
#define NST2  8            // 256/32

#define SROW 80            // stage tile row stride bytes -> conflict-free LDSM
#define SH   264           // H1 row stride (bf16 elems) = 528B
#define DS   65            // d1s fp32 row stride

// ---- GEMM1 stage layout (bytes within stage) ----
#define A_HI 0             // 128 x 80
#define A_LO 10240
#define B_HI 20480         // 256 x 80
#define B_LO 40960
#define STG  61440         // x3 stages: [0, 184320)
// ---- phase-2 layout (aliases stage region; GEMM1 retired first) ----
#define OFF_H1HI 0         // 128 x 264 bf16 = 67584
#define OFF_H1LO 67584
#define OFF_D1S  135168    // 128 x 65 fp32 = 33280
#define OFF_B2   168448    // 2 stages x 20480 (hi 10240 | lo 10240)
#define B2_STG   20480
// ---- persistent misc ----
#define OFF_ADJW 209408
#define OFF_ADJI 211200
#define OFF_DINV 212992
#define OFF_POOL 213248
#define SMEM_BYTES 214528

// ---- pre-split operands (filled by prep kernels) ----
__device__ __nv_bfloat16 g_xh[(size_t)BMAX * NNODE * DIM];
__device__ __nv_bfloat16 g_xl[(size_t)BMAX * NNODE * DIM];
__device__ __nv_bfloat16 g_W1hi[C1 * DIM];
__device__ __nv_bfloat16 g_W1lo[C1 * DIM];
__device__ __nv_bfloat16 g_W2hi[C2 * C1];
__device__ __nv_bfloat16 g_W2lo[C2 * C1];

__device__ __forceinline__ void mma_bf16(float* c, const unsigned* a, const unsigned* b) {
    asm volatile(
        "mma.sync.aligned.m16n8k16.row.col.f32.bf16.bf16.f32 "
        "{%0,%1,%2,%3}, {%4,%5,%6,%7}, {%8,%9}, {%0,%1,%2,%3};\n"
        : "+f"(c[0]), "+f"(c[1]), "+f"(c[2]), "+f"(c[3])
        : "r"(a[0]), "r"(a[1]), "r"(a[2]), "r"(a[3]), "r"(b[0]), "r"(b[1]));
}
__device__ __forceinline__ void ldsm4(unsigned* r, uint32_t addr) {
    asm volatile("ldmatrix.sync.aligned.m8n8.x4.shared.b16 {%0,%1,%2,%3}, [%4];"
        : "=r"(r[0]), "=r"(r[1]), "=r"(r[2]), "=r"(r[3]) : "r"(addr));
}
__device__ __forceinline__ void cpa16(uint32_t dst, const void* src) {
    asm volatile("cp.async.cg.shared.global [%0], [%1], 16;" :: "r"(dst), "l"(src));
}
__device__ __forceinline__ void cpa16z(uint32_t dst, const void* src, int srcsize) {
    asm volatile("cp.async.cg.shared.global [%0], [%1], 16, %2;"
                 :: "r"(dst), "l"(src), "r"(srcsize));
}
#define CPA_COMMIT() asm volatile("cp.async.commit_group;" ::: "memory")
#define CPA_WAIT0()  asm volatile("cp.async.wait_group 0;" ::: "memory")
#define CPA_WAIT1()  asm volatile("cp.async.wait_group 1;" ::: "memory")

__device__ __forceinline__ unsigned packbf(__nv_bfloat16 a, __nv_bfloat16 b) {
    return ((unsigned)__bfloat16_as_ushort(b) << 16) | (unsigned)__bfloat16_as_ushort(a);
}

// ==================== prep: split x into bf16 hi/lo ====================
__global__ void prep_x(const float4* __restrict__ x4, int n4) {
    int i = blockIdx.x * blockDim.x + threadIdx.x;
    if (i >= n4) return;
    float4 v = x4[i];
    __nv_bfloat16 h0 = __float2bfloat16(v.x), h1 = __float2bfloat16(v.y);
    __nv_bfloat16 h2 = __float2bfloat16(v.z), h3 = __float2bfloat16(v.w);
    __nv_bfloat16 l0 = __float2bfloat16(v.x - __bfloat162float(h0));
    __nv_bfloat16 l1 = __float2bfloat16(v.y - __bfloat162float(h1));
    __nv_bfloat16 l2 = __float2bfloat16(v.z - __bfloat162float(h2));
    __nv_bfloat16 l3 = __float2bfloat16(v.w - __bfloat162float(h3));
    *(uint2*)(g_xh + (size_t)i * 4) = make_uint2(packbf(h0, h1), packbf(h2, h3));
    *(uint2*)(g_xl + (size_t)i * 4) = make_uint2(packbf(l0, l1), packbf(l2, l3));
}

// ==================== prep: split + transpose weights ====================
__global__ void prep_weights(const float* __restrict__ W1, const float* __restrict__ W2) {
    int idx = blockIdx.x * blockDim.x + threadIdx.x;
    if (idx < C1 * DIM) {                       // W1 [768][256] -> [256][768]
        int k = idx >> 8, n = idx & 255;
        float v = W1[idx];
        __nv_bfloat16 h = __float2bfloat16(v);
        g_W1hi[n * DIM + k] = h;
        g_W1lo[n * DIM + k] = __float2bfloat16(v - __bfloat162float(h));
    } else if (idx < C1 * DIM + C1 * C2) {      // W2 [256][128] -> [128][256]
        int j = idx - C1 * DIM;
        int k = j >> 7, n = j & 127;
        float v = W2[j];
        __nv_bfloat16 h = __float2bfloat16(v);
        g_W2hi[n * C1 + k] = h;
        g_W2lo[n * C1 + k] = __float2bfloat16(v - __bfloat162float(h));
    }
}

// =========================== main fused kernel ===========================
__global__ void __launch_bounds__(TPB, 1)
gnn_fused(const float* __restrict__ b1, const float* __restrict__ b2,
          const float* __restrict__ Wf, const float* __restrict__ bf,
          float* __restrict__ out)
{
    extern __shared__ unsigned char smem[];
    const uint32_t sbase = (uint32_t)__cvta_generic_to_shared(smem);

    float* adjw   = (float*)(smem + OFF_ADJW);
    int*   adji   = (int*)(smem + OFF_ADJI);
    float* dinv   = (float*)(smem + OFF_DINV);
    float* pooled = (float*)(smem + OFF_POOL);
    float* d1s    = (float*)(smem + OFF_D1S);

    const int tid  = threadIdx.x;
    const int lane = tid & 31;
    const int wid  = tid >> 5;    // 0..15
    const int wm   = wid >> 2;    // 0..3  (m32 block)
    const int wn   = wid & 3;     // 0..3  (n64 G1 / n32 G2)
    const int tr   = lane >> 2;
    const int tc   = lane & 3;
    const int b0   = blockIdx.x * BT;

    // ldmatrix lane pattern
    const int lrow = (lane & 7) + ((lane >> 3) & 1) * 8;
    const int lkb  = (lane >> 4) * 16;

    // ---- adjacency (exact fp32) ----
    if (tid < NNODE) {
        int r = tid / 7, c = tid % 7;
        int nr = min(r + 1, 6) - max(r - 1, 0) + 1;
        int nc = min(c + 1, 6) - max(c - 1, 0) + 1;
        dinv[tid] = 1.0f / sqrtf((float)(nr * nc));
    }
    __syncthreads();
    if (tid < NNODE) {
        int r = tid / 7, c = tid % 7;
        float di = dinv[tid];
        int t = 0;
        for (int dr = -1; dr <= 1; dr++)
            for (int dc = -1; dc <= 1; dc++) {
                int rr = r + dr, cc = c + dc;
                if (rr >= 0 && rr < 7 && cc >= 0 && cc < 7) {
                    int j = rr * 7 + cc;
                    adji[tid * 9 + t] = j;
                    adjw[tid * 9 + t] = di * dinv[j];
                    t++;
                }
            }
        for (; t < 9; t++) { adji[tid * 9 + t] = 0; adjw[tid * 9 + t] = 0.0f; }
    }

    // ---- staging thread assignments (512 threads) ----
    // A: 128 rows x 4 chunks x 2 (hi/lo) = 1024 ops -> 2 chunks per thread
    const int arow  = tid >> 2;
    const int aq    = tid & 3;
    const int ahilo = aq >> 1;          // 0=hi, 1=lo
    const int ac0   = (aq & 1) * 2;     // first of 2 chunks
    const int ag    = arow >> 6;
    const int anode = arow & 63;
    const int asz   = (anode < NNODE) ? 16 : 0;
    const int anc   = min(anode, NNODE - 1);
    const __nv_bfloat16* pxa =
        (ahilo ? g_xl : g_xh) + ((size_t)(b0 + ag) * NNODE + anc) * DIM + ac0 * 8;
    const uint32_t adst = (uint32_t)((ahilo ? A_LO : A_HI) + arow * SROW + ac0 * 16);
    // B: 256 n x 4 chunks x 2 = 2048 ops -> 4 per thread (n = tid>>1, hilo = tid&1)
    const int bn    = tid >> 1;
    const int bhilo = tid & 1;
    const __nv_bfloat16* pw1 = (bhilo ? g_W1lo : g_W1hi) + (size_t)bn * DIM;
    const uint32_t bdst = (uint32_t)((bhilo ? B_LO : B_HI) + bn * SROW);

    // frag base byte offsets
    const uint32_t aoff = (uint32_t)((wm * 32 + lrow) * SROW + lkb);
    const uint32_t boff = (uint32_t)((wn * 64 + lrow) * SROW + lkb);

    // ---- GEMM1 stage filler ----
    auto fill1 = [&](int kt, uint32_t stg) {
        const int ke = kt * 32;
        #pragma unroll
        for (int c = 0; c < 2; c++)
            cpa16z(sbase + stg + adst + c * 16, pxa + ke + c * 8, asz);
        #pragma unroll
        for (int c = 0; c < 4; c++)
            cpa16(sbase + stg + bdst + c * 16, pw1 + ke + c * 8);
        CPA_COMMIT();
    };

    // =========== GEMM1: T1 = X @ W1  (128 x 256 x 768, bf16x3) ===========
    float acc[16][4];                 // warp tile m32 x n64
    #pragma unroll
    for (int j = 0; j < 16; j++)
        #pragma unroll
        for (int k = 0; k < 4; k++) acc[j][k] = 0.0f;

    fill1(0, 0);
    fill1(1, STG);

    #pragma unroll 1
    for (int kt = 0; kt < NST1; kt++) {
        const uint32_t cs = (uint32_t)(kt % 3) * STG;
        if (kt < NST1 - 2) CPA_WAIT1(); else CPA_WAIT0();
        __syncthreads();
        if (kt + 2 < NST1) fill1(kt + 2, (uint32_t)((kt + 2) % 3) * STG);

        #pragma unroll
        for (int kh = 0; kh < 2; kh++) {
            unsigned afh[2][4], afl[2][4];
            #pragma unroll
            for (int mi = 0; mi < 2; mi++) {
                ldsm4(afh[mi], sbase + cs + A_HI + aoff + mi * 16 * SROW + kh * 32);
                ldsm4(afl[mi], sbase + cs + A_LO + aoff + mi * 16 * SROW + kh * 32);
            }
            #pragma unroll
            for (int p = 0; p < 4; p++) {
                unsigned bh4[4], bl4[4];
                ldsm4(bh4, sbase + cs + B_HI + boff + p * 16 * SROW + kh * 32);
                ldsm4(bl4, sbase + cs + B_LO + boff + p * 16 * SROW + kh * 32);
                #pragma unroll
                for (int h = 0; h < 2; h++) {
                    const int nj = p * 2 + h;
                    unsigned bh[2] = { bh4[h], bh4[2 + h] };
                    unsigned bl[2] = { bl4[h], bl4[2 + h] };
                    #pragma unroll
                    for (int mi = 0; mi < 2; mi++) {
                        mma_bf16(acc[mi*8+nj], afh[mi], bh);
                        mma_bf16(acc[mi*8+nj], afh[mi], bl);
                        mma_bf16(acc[mi*8+nj], afl[mi], bh);
                    }
                }
            }
        }
    }
    __syncthreads();

    // GEMM2 B staging: 128 n x 4 chunks x 2 = 1024 ops -> 2 chunks per thread
    const int b2n    = tid >> 2;
    const int b2q    = tid & 3;
    const int b2hilo = b2q >> 1;
    const int b2c0   = (b2q & 1) * 2;
    const __nv_bfloat16* pw2 = (b2hilo ? g_W2lo : g_W2hi) + (size_t)b2n * C1 + b2c0 * 8;
    const uint32_t b2dst = (uint32_t)((b2hilo ? 10240 : 0) + b2n * SROW + b2c0 * 16);
    auto fill2 = [&](int kt, uint32_t stg) {
        #pragma unroll
        for (int c = 0; c < 2; c++)
            cpa16(sbase + stg + b2dst + c * 16, pw2 + kt * 32 + c * 8);
        CPA_COMMIT();
    };
    fill2(0, OFF_B2);       // latency absorbed by epilogue 1

    // ===== epilogue 1: H1 = relu(ADJ @ T1 + b1), split bf16 hi/lo =====
    __nv_bfloat16* H1hi = (__nv_bfloat16*)(smem + OFF_H1HI);
    __nv_bfloat16* H1lo = (__nv_bfloat16*)(smem + OFF_H1LO);
    #pragma unroll 1
    for (int ci = 0; ci < 4; ci++) {
        if (wn == ci) {
            #pragma unroll
            for (int mi = 0; mi < 2; mi++)
                #pragma unroll
                for (int nj = 0; nj < 8; nj++) {
                    const int row = wm*32 + mi*16 + tr;
                    const int col = nj*8 + tc*2;
                    float* a = acc[mi*8+nj];
                    d1s[row * DS + col]           = a[0];
                    d1s[row * DS + col + 1]       = a[1];
                    d1s[(row + 8) * DS + col]     = a[2];
                    d1s[(row + 8) * DS + col + 1] = a[3];
                }
        }
        __syncthreads();
        for (int task = tid; task < BT * NNODE * 64; task += TPB) {
            const int cl   = task & 63;
            const int rest = task >> 6;
            const int g    = (rest >= NNODE) ? 1 : 0;
            const int i    = rest - g * NNODE;
            float s = __ldg(&b1[ci * 64 + cl]);
            #pragma unroll
            for (int t = 0; t < 9; t++)
                s += adjw[i*9+t] * d1s[(g*64 + adji[i*9+t]) * DS + cl];
            s = fmaxf(s, 0.0f);
            __nv_bfloat16 h = __float2bfloat16(s);
            H1hi[(g*64 + i) * SH + ci*64 + cl] = h;
            H1lo[(g*64 + i) * SH + ci*64 + cl] = __float2bfloat16(s - __bfloat162float(h));
        }
        __syncthreads();
    }

    // =========== GEMM2: T2 = H1 @ W2  (128 x 128 x 256, bf16x3) ===========
    float acc2[8][4];                 // warp tile m32 x n32
    #pragma unroll
    for (int j = 0; j < 8; j++)
        #pragma unroll
        for (int k = 0; k < 4; k++) acc2[j][k] = 0.0f;

    const uint32_t hoff  = (uint32_t)((wm * 32 + lrow) * (SH * 2) + lkb);
    const uint32_t b2off = (uint32_t)((wn * 32 + lrow) * SROW + lkb);

    #pragma unroll 1
    for (int kt = 0; kt < NST2; kt++) {
        const uint32_t cs = OFF_B2 + (uint32_t)(kt & 1) * B2_STG;
        CPA_WAIT0();
        __syncthreads();
        if (kt + 1 < NST2) fill2(kt + 1, OFF_B2 + (uint32_t)((kt + 1) & 1) * B2_STG);

        #pragma unroll
        for (int kh = 0; kh < 2; kh++) {
            unsigned afh[2][4], afl[2][4];
            #pragma unroll
            for (int mi = 0; mi < 2; mi++) {
                ldsm4(afh[mi], sbase + OFF_H1HI + hoff + mi*16*(SH*2) + kt*64 + kh*32);
                ldsm4(afl[mi], sbase + OFF_H1LO + hoff + mi*16*(SH*2) + kt*64 + kh*32);
            }
            #pragma unroll
            for (int p = 0; p < 2; p++) {
                unsigned bh4[4], bl4[4];
                ldsm4(bh4, sbase + cs + b2off + p*16*SROW + kh*32);
                ldsm4(bl4, sbase + cs + 10240 + b2off + p*16*SROW + kh*32);
                #pragma unroll
                for (int h = 0; h < 2; h++) {
                    const int nj = p*2 + h;
                    unsigned bh[2] = { bh4[h], bh4[2+h] };
                    unsigned bl[2] = { bl4[h], bl4[2+h] };
                    #pragma unroll
                    for (int mi = 0; mi < 2; mi++) {
                        mma_bf16(acc2[mi*4+nj], afh[mi], bh);
                        mma_bf16(acc2[mi*4+nj], afh[mi], bl);
                        mma_bf16(acc2[mi*4+nj], afl[mi], bh);
                    }
                }
            }
        }
    }
    __syncthreads();

    // ======== epilogue 2: ADJ + bias + relu + mean-pool + head ========
    #pragma unroll 1
    for (int ci = 0; ci < 2; ci++) {
        if ((wn >> 1) == ci) {
            #pragma unroll
            for (int mi = 0; mi < 2; mi++)
                #pragma unroll
                for (int nj = 0; nj < 4; nj++) {
                    const int row = wm*32 + mi*16 + tr;
                    const int col = (wn & 1)*32 + nj*8 + tc*2;
                    float* a = acc2[mi*4+nj];
                    d1s[row * DS + col]           = a[0];
                    d1s[row * DS + col + 1]       = a[1];
                    d1s[(row + 8) * DS + col]     = a[2];
                    d1s[(row + 8) * DS + col + 1] = a[3];
                }
        }
        __syncthreads();
        {
            const int quarter = tid & 3;
            const int rest    = tid >> 2;       // 0..127
            const int g       = rest >> 6;
            const int cl      = rest & 63;
            const float bias  = __ldg(&b2[ci * 64 + cl]);
            const int i0   = quarter * 13;
            const int icnt = (quarter < 3) ? 13 : 10;
            float ps = 0.0f;
            for (int ii = 0; ii < icnt; ii++) {
                const int i = i0 + ii;
                float s = bias;
                #pragma unroll
                for (int t = 0; t < 9; t++)
                    s += adjw[i*9+t] * d1s[(g*64 + adji[i*9+t]) * DS + cl];
                ps += fmaxf(s, 0.0f);
            }
            ps += __shfl_xor_sync(0xFFFFFFFFu, ps, 1);
            ps += __shfl_xor_sync(0xFFFFFFFFu, ps, 2);
            if (quarter == 0) pooled[g * C2 + ci * 64 + cl] = ps * (1.0f / 49.0f);
        }
        __syncthreads();
    }

    if (tid < BT * NCLS) {
        const int g = tid / NCLS, o = tid - g * NCLS;
        float s = __ldg(&bf[o]);
        const float* pp = pooled + g * C2;
        #pragma unroll 8
        for (int k = 0; k < C2; k++) s += pp[k] * __ldg(&Wf[k * NCLS + o]);
        out[(size_t)(b0 + g) * NCLS + o] = s;
    }
}

extern "C" void kernel_launch(void* const* d_in, const int* in_sizes, int n_in,
                              void* d_out, int out_size)
{
    const float* x  = (const float*)d_in[0];
    const float* W1 = (const float*)d_in[1];
    const float* b1 = (const float*)d_in[2];
    const float* W2 = (const float*)d_in[3];
    const float* b2 = (const float*)d_in[4];
    const float* Wf = (const float*)d_in[5];
    const float* bf = (const float*)d_in[6];
    float* out = (float*)d_out;

    const int B  = in_sizes[0] / (NNODE * DIM);   // 4096
    const int n4 = in_sizes[0] / 4;

    prep_x<<<(n4 + 255) / 256, 256>>>((const float4*)x, n4);
    prep_weights<<<(C1 * DIM + C1 * C2 + 255) / 256, 256>>>(W1, W2);

    cudaFuncSetAttribute(gnn_fused, cudaFuncAttributeMaxDynamicSharedMemorySize, SMEM_BYTES);
    gnn_fused<<<B / BT, TPB, SMEM_BYTES>>>(b1, b2, Wf, bf, out);
}

// round 12
// speedup vs baseline: 1.2893x; 1.2558x over previous
#include <cuda_runtime.h>
#include <cuda_fp16.h>
#include <stdint.h>

#define TPB   512
#define NNODE 49
#define BT    2
#define BMAX  4096
#define DIM   768
#define C1    256
#define C2    128
#define NCLS  13
#define NST1  24           // 768/32 K32 stages
#define NST2  8            // 256/32

#define W1SCALE 1024.0f
#define W2SCALE 512.0f
#define INV1    (1.0f/1024.0f)
#define INV2    (1.0f/512.0f)

#define SROW 80            // stage tile row stride bytes -> conflict-free LDSM
#define SH   264           // H1 row stride (fp16 elems) = 528B
#define DS   65            // d1s fp32 row stride

// ---- GEMM1 stage layout (bytes within stage) ----
#define A_T  0             // 128 x 80 (fp16 single)
#define B_HI 10240         // 256 x 80
#define B_LO 30720
#define STG  51200         // x3 stages: [0, 153600)
// ---- phase-2 layout (aliases stage region; GEMM1 retired first) ----
#define OFF_H1   0         // 128 x 264 fp16 = 67584
#define OFF_D1S  67584     // 128 x 65 fp32 = 33280
#define OFF_B2   100864    // 2 stages x 20480 (hi 10240 | lo 10240)
#define B2_STG   20480
// ---- persistent misc (above all stage regions) ----
#define OFF_ADJW 153600
#define OFF_ADJI 155392
#define OFF_DINV 157184
#define OFF_POOL 157440
#define SMEM_BYTES 158464

// ---- pre-split operands (filled by prep kernels) ----
__device__ __half g_x[(size_t)BMAX * NNODE * DIM];
__device__ __half g_W1hi[C1 * DIM];
__device__ __half g_W1lo[C1 * DIM];
__device__ __half g_W2hi[C2 * C1];
__device__ __half g_W2lo[C2 * C1];

__device__ __forceinline__ void mma_f16(float* c, const unsigned* a, const unsigned* b) {
    asm volatile(
        "mma.sync.aligned.m16n8k16.row.col.f32.f16.f16.f32 "
        "{%0,%1,%2,%3}, {%4,%5,%6,%7}, {%8,%9}, {%0,%1,%2,%3};\n"
        : "+f"(c[0]), "+f"(c[1]), "+f"(c[2]), "+f"(c[3])
        : "r"(a[0]), "r"(a[1]), "r"(a[2]), "r"(a[3]), "r"(b[0]), "r"(b[1]));
}
__device__ __forceinline__ void ldsm4(unsigned* r, uint32_t addr) {
    asm volatile("ldmatrix.sync.aligned.m8n8.x4.shared.b16 {%0,%1,%2,%3}, [%4];"
        : "=r"(r[0]), "=r"(r[1]), "=r"(r[2]), "=r"(r[3]) : "r"(addr));
}
__device__ __forceinline__ void cpa16(uint32_t dst, const void* src) {
    asm volatile("cp.async.cg.shared.global [%0], [%1], 16;" :: "r"(dst), "l"(src));
}
__device__ __forceinline__ void cpa16z(uint32_t dst, const void* src, int srcsize) {
    asm volatile("cp.async.cg.shared.global [%0], [%1], 16, %2;"
                 :: "r"(dst), "l"(src), "r"(srcsize));
}
#define CPA_COMMIT() asm volatile("cp.async.commit_group;" ::: "memory")
#define CPA_WAIT0()  asm volatile("cp.async.wait_group 0;" ::: "memory")
#define CPA_WAIT1()  asm volatile("cp.async.wait_group 1;" ::: "memory")

__device__ __forceinline__ unsigned packh(__half a, __half b) {
    return ((unsigned)__half_as_ushort(b) << 16) | (unsigned)__half_as_ushort(a);
}

// ==================== prep: x -> fp16 ====================
__global__ void prep_x(const float4* __restrict__ x4, int n4) {
    int i = blockIdx.x * blockDim.x + threadIdx.x;
    if (i >= n4) return;
    float4 v = x4[i];
    *(uint2*)(g_x + (size_t)i * 4) =
        make_uint2(packh(__float2half(v.x), __float2half(v.y)),
                   packh(__float2half(v.z), __float2half(v.w)));
}

// ==================== prep: scale + split + transpose weights ====================
__global__ void prep_weights(const float* __restrict__ W1, const float* __restrict__ W2) {
    int idx = blockIdx.x * blockDim.x + threadIdx.x;
    if (idx < C1 * DIM) {                       // W1 [768][256] -> [256][768], x1024
        int k = idx >> 8, n = idx & 255;
        float v = W1[idx] * W1SCALE;
        __half h = __float2half(v);
        g_W1hi[n * DIM + k] = h;
        g_W1lo[n * DIM + k] = __float2half(v - __half2float(h));
    } else if (idx < C1 * DIM + C1 * C2) {      // W2 [256][128] -> [128][256], x512
        int j = idx - C1 * DIM;
        int k = j >> 7, n = j & 127;
        float v = W2[j] * W2SCALE;
        __half h = __float2half(v);
        g_W2hi[n * C1 + k] = h;
        g_W2lo[n * C1 + k] = __float2half(v - __half2float(h));
    }
}

// =========================== main fused kernel ===========================
__global__ void __launch_bounds__(TPB, 1)
gnn_fused(const float* __restrict__ b1, const float* __restrict__ b2,
          const float* __restrict__ Wf, const float* __restrict__ bf,
          float* __restrict__ out)
{
    extern __shared__ unsigned char smem[];
    const uint32_t sbase = (uint32_t)__cvta_generic_to_shared(smem);

    float* adjw   = (float*)(smem + OFF_ADJW);
    int*   adji   = (int*)(smem + OFF_ADJI);
    float* dinv   = (float*)(smem + OFF_DINV);
    float* pooled = (float*)(smem + OFF_POOL);
    float* d1s    = (float*)(smem + OFF_D1S);

    const int tid  = threadIdx.x;
    const int lane = tid & 31;
    const int wid  = tid >> 5;    // 0..15
    const int wm   = wid >> 2;    // 0..3  (m32 block)
    const int wn   = wid & 3;     // 0..3  (n64 G1 / n32 G2)
    const int tr   = lane >> 2;
    const int tc   = lane & 3;
    const int b0   = blockIdx.x * BT;

    // ldmatrix lane pattern
    const int lrow = (lane & 7) + ((lane >> 3) & 1) * 8;
    const int lkb  = (lane >> 4) * 16;

    // ---- adjacency (exact fp32) ----
    if (tid < NNODE) {
        int r = tid / 7, c = tid % 7;
        int nr = min(r + 1, 6) - max(r - 1, 0) + 1;
        int nc = min(c + 1, 6) - max(c - 1, 0) + 1;
        dinv[tid] = 1.0f / sqrtf((float)(nr * nc));
    }
    __syncthreads();
    if (tid < NNODE) {
        int r = tid / 7, c = tid % 7;
        float di = dinv[tid];
        int t = 0;
        for (int dr = -1; dr <= 1; dr++)
            for (int dc = -1; dc <= 1; dc++) {
                int rr = r + dr, cc = c + dc;
                if (rr >= 0 && rr < 7 && cc >= 0 && cc < 7) {
                    int j = rr * 7 + cc;
                    adji[tid * 9 + t] = j;
                    adjw[tid * 9 + t] = di * dinv[j];
                    t++;
                }
            }
        for (; t < 9; t++) { adji[tid * 9 + t] = 0; adjw[tid * 9 + t] = 0.0f; }
    }

    // ---- staging thread assignments (512 threads) ----
    // A: 128 rows x 4 chunks (fp16 single) = 512 ops -> 1 per thread
    const int arow  = tid >> 2;
    const int ac    = tid & 3;
    const int ag    = arow >> 6;
    const int anode = arow & 63;
    const int asz   = (anode < NNODE) ? 16 : 0;
    const int anc   = min(anode, NNODE - 1);
    const __half* pxa = g_x + ((size_t)(b0 + ag) * NNODE + anc) * DIM + ac * 8;
    const uint32_t adst = (uint32_t)(arow * SROW + ac * 16);
    // B: 256 n x 4 chunks x 2 (hi/lo) = 2048 ops -> 4 per thread
    const int bn    = tid >> 1;
    const int bhilo = tid & 1;
    const __half* pw1 = (bhilo ? g_W1lo : g_W1hi) + (size_t)bn * DIM;
    const uint32_t bdst = (uint32_t)((bhilo ? B_LO : B_HI) + bn * SROW);

    // frag base byte offsets
    const uint32_t aoff = (uint32_t)((wm * 32 + lrow) * SROW + lkb);
    const uint32_t boff = (uint32_t)((wn * 64 + lrow) * SROW + lkb);

    // ---- GEMM1 stage filler ----
    auto fill1 = [&](int kt, uint32_t stg) {
        const int ke = kt * 32;
        cpa16z(sbase + stg + A_T + adst, pxa + ke, asz);
        #pragma unroll
        for (int c = 0; c < 4; c++)
            cpa16(sbase + stg + bdst + c * 16, pw1 + ke + c * 8);
        CPA_COMMIT();
    };

    // ===== GEMM1: T1 = X @ (W1*S1)  (128 x 256 x 768, fp16x2) =====
    float acc[16][4];                 // warp tile m32 x n64
    #pragma unroll
    for (int j = 0; j < 16; j++)
        #pragma unroll
        for (int k = 0; k < 4; k++) acc[j][k] = 0.0f;

    fill1(0, 0);
    fill1(1, STG);

    #pragma unroll 1
    for (int kt = 0; kt < NST1; kt++) {
        const uint32_t cs = (uint32_t)(kt % 3) * STG;
        if (kt < NST1 - 2) CPA_WAIT1(); else CPA_WAIT0();
        __syncthreads();
        if (kt + 2 < NST1) fill1(kt + 2, (uint32_t)((kt + 2) % 3) * STG);

        #pragma unroll
        for (int kh = 0; kh < 2; kh++) {
            unsigned af[2][4];
            #pragma unroll
            for (int mi = 0; mi < 2; mi++)
                ldsm4(af[mi], sbase + cs + A_T + aoff + mi * 16 * SROW + kh * 32);
            #pragma unroll
            for (int p = 0; p < 4; p++) {
                unsigned bh4[4], bl4[4];
                ldsm4(bh4, sbase + cs + B_HI + boff + p * 16 * SROW + kh * 32);
                ldsm4(bl4, sbase + cs + B_LO + boff + p * 16 * SROW + kh * 32);
                #pragma unroll
                for (int h = 0; h < 2; h++) {
                    const int nj = p * 2 + h;
                    unsigned bh[2] = { bh4[h], bh4[2 + h] };
                    unsigned bl[2] = { bl4[h], bl4[2 + h] };
                    #pragma unroll
                    for (int mi = 0; mi < 2; mi++) {
                        mma_f16(acc[mi*8+nj], af[mi], bh);
                        mma_f16(acc[mi*8+nj], af[mi], bl);
                    }
                }
            }
        }
    }
    __syncthreads();

    // GEMM2 B staging: 128 n x 4 chunks x 2 = 1024 ops -> 2 chunks per thread
    const int b2n    = tid >> 2;
    const int b2q    = tid & 3;
    const int b2hilo = b2q >> 1;
    const int b2c0   = (b2q & 1) * 2;
    const __half* pw2 = (b2hilo ? g_W2lo : g_W2hi) + (size_t)b2n * C1 + b2c0 * 8;
    const uint32_t b2dst = (uint32_t)((b2hilo ? 10240 : 0) + b2n * SROW + b2c0 * 16);
    auto fill2 = [&](int kt, uint32_t stg) {
        #pragma unroll
        for (int c = 0; c < 2; c++)
            cpa16(sbase + stg + b2dst + c * 16, pw2 + kt * 32 + c * 8);
        CPA_COMMIT();
    };
    fill2(0, OFF_B2);       // latency absorbed by epilogue 1

    // ===== epilogue 1: H1 = fp16(relu(ADJ @ T1 * INV1 + b1)) =====
    __half* H1 = (__half*)(smem + OFF_H1);
    #pragma unroll 1
    for (int ci = 0; ci < 4; ci++) {
        if (wn == ci) {
            #pragma unroll
            for (int mi = 0; mi < 2; mi++)
                #pragma unroll
                for (int nj = 0; nj < 8; nj++) {
                    const int row = wm*32 + mi*16 + tr;
                    const int col = nj*8 + tc*2;
                    float* a = acc[mi*8+nj];
                    d1s[row * DS + col]           = a[0];
                    d1s[row * DS + col + 1]       = a[1];
                    d1s[(row + 8) * DS + col]     = a[2];
                    d1s[(row + 8) * DS + col + 1] = a[3];
                }
        }
        __syncthreads();
        for (int task = tid; task < BT * NNODE * 64; task += TPB) {
            const int cl   = task & 63;
            const int rest = task >> 6;
            const int g    = (rest >= NNODE) ? 1 : 0;
            const int i    = rest - g * NNODE;
            float dot = 0.0f;
            #pragma unroll
            for (int t = 0; t < 9; t++)
                dot += adjw[i*9+t] * d1s[(g*64 + adji[i*9+t]) * DS + cl];
            float s = fmaxf(fmaf(dot, INV1, __ldg(&b1[ci * 64 + cl])), 0.0f);
            H1[(g*64 + i) * SH + ci*64 + cl] = __float2half(s);
        }
        __syncthreads();
    }

    // ===== GEMM2: T2 = H1 @ (W2*S2)  (128 x 128 x 256, fp16x2) =====
    float acc2[8][4];                 // warp tile m32 x n32
    #pragma unroll
    for (int j = 0; j < 8; j++)
        #pragma unroll
        for (int k = 0; k < 4; k++) acc2[j][k] = 0.0f;

    const uint32_t hoff  = (uint32_t)((wm * 32 + lrow) * (SH * 2) + lkb);
    const uint32_t b2off = (uint32_t)((wn * 32 + lrow) * SROW + lkb);

    #pragma unroll 1
    for (int kt = 0; kt < NST2; kt++) {
        const uint32_t cs = OFF_B2 + (uint32_t)(kt & 1) * B2_STG;
        CPA_WAIT0();
        __syncthreads();
        if (kt + 1 < NST2) fill2(kt + 1, OFF_B2 + (uint32_t)((kt + 1) & 1) * B2_STG);

        #pragma unroll
        for (int kh = 0; kh < 2; kh++) {
            unsigned af[2][4];
            #pragma unroll
            for (int mi = 0; mi < 2; mi++)
                ldsm4(af[mi], sbase + OFF_H1 + hoff + mi*16*(SH*2) + kt*64 + kh*32);
            #pragma unroll
            for (int p = 0; p < 2; p++) {
                unsigned bh4[4], bl4[4];
                ldsm4(bh4, sbase + cs + b2off + p*16*SROW + kh*32);
                ldsm4(bl4, sbase + cs + 10240 + b2off + p*16*SROW + kh*32);
                #pragma unroll
                for (int h = 0; h < 2; h++) {
                    const int nj = p*2 + h;
                    unsigned bh[2] = { bh4[h], bh4[2+h] };
                    unsigned bl[2] = { bl4[h], bl4[2+h] };
                    #pragma unroll
                    for (int mi = 0; mi < 2; mi++) {
                        mma_f16(acc2[mi*4+nj], af[mi], bh);
                        mma_f16(acc2[mi*4+nj], af[mi], bl);
                    }
                }
            }
        }
    }
    __syncthreads();

    // ======== epilogue 2: ADJ + bias + relu + mean-pool + head ========
    #pragma unroll 1
    for (int ci = 0; ci < 2; ci++) {
        if ((wn >> 1) == ci) {
            #pragma unroll
            for (int mi = 0; mi < 2; mi++)
                #pragma unroll
                for (int nj = 0; nj < 4; nj++) {
                    const int row = wm*32 + mi*16 + tr;
                    const int col = (wn & 1)*32 + nj*8 + tc*2;
                    float* a = acc2[mi*4+nj];
                    d1s[row * DS + col]           = a[0];
                    d1s[row * DS + col + 1]       = a[1];
                    d1s[(row + 8) * DS + col]     = a[2];
                    d1s[(row + 8) * DS + col + 1] = a[3];
                }
        }
        __syncthreads();
        {
            const int quarter = tid & 3;
            const int rest    = tid >> 2;       // 0..127
            const int g       = rest >> 6;
            const int cl      = rest & 63;
            const float bias  = __ldg(&b2[ci * 64 + cl]);
            const int i0   = quarter * 13;
            const int icnt = (quarter < 3) ? 13 : 10;
            float ps = 0.0f;
            for (int ii = 0; ii < icnt; ii++) {
                const int i = i0 + ii;
                float dot = 0.0f;
                #pragma unroll
                for (int t = 0; t < 9; t++)
                    dot += adjw[i*9+t] * d1s[(g*64 + adji[i*9+t]) * DS + cl];
                ps += fmaxf(fmaf(dot, INV2, bias), 0.0f);
            }
            ps += __shfl_xor_sync(0xFFFFFFFFu, ps, 1);
            ps += __shfl_xor_sync(0xFFFFFFFFu, ps, 2);
            if (quarter == 0) pooled[g * C2 + ci * 64 + cl] = ps * (1.0f / 49.0f);
        }
        __syncthreads();
    }

    if (tid < BT * NCLS) {
        const int g = tid / NCLS, o = tid - g * NCLS;
        float s = __ldg(&bf[o]);
        const float* pp = pooled + g * C2;
        #pragma unroll 8
        for (int k = 0; k < C2; k++) s += pp[k] * __ldg(&Wf[k * NCLS + o]);
        out[(size_t)(b0 + g) * NCLS + o] = s;
    }
}

extern "C" void kernel_launch(void* const* d_in, const int* in_sizes, int n_in,
                              void* d_out, int out_size)
{
    const float* x  = (const float*)d_in[0];
    const float* W1 = (const float*)d_in[1];
    const float* b1 = (const float*)d_in[2];
    const float* W2 = (const float*)d_in[3];
    const float* b2 = (const float*)d_in[4];
    const float* Wf = (const float*)d_in[5];
    const float* bf = (const float*)d_in[6];
    float* out = (float*)d_out;

    const int B  = in_sizes[0] / (NNODE * DIM);   // 4096
    const int n4 = in_sizes[0] / 4;

    prep_x<<<(n4 + 255) / 256, 256>>>((const float4*)x, n4);
    prep_weights<<<(C1 * DIM + C1 * C2 + 255) / 256, 256>>>(W1, W2);

    cudaFuncSetAttribute(gnn_fused, cudaFuncAttributeMaxDynamicSharedMemorySize, SMEM_BYTES);
    gnn_fused<<<B / BT, TPB, SMEM_BYTES>>>(b1, b2, Wf, bf, out);
}

// round 13
// speedup vs baseline: 1.9412x; 1.5057x over previous
#include <cuda_runtime.h>
#include <cuda_fp16.h>
#include <stdint.h>

#define TPB   512
#define NNODE 49
#define BT    2
#define BMAX  4096
#define DIM   768
#define C1    256
#define C2    128
#define NCLS  13
#define NST1  24           // 768/32 K32 stages
#define NST2  8            // 256/32

#define SROW 80            // stage tile row stride bytes -> conflict-free LDSM
#define SH   264           // H1 row stride (fp16 elems) = 528B
#define DS   65            // d1s fp32 row stride

// ---- GEMM1 stage layout (bytes within stage) ----
#define A_T  0             // 128 x 80 (fp16)
#define B_T  10240         // 256 x 80 (fp16)
#define STG  30720         // x3 stages: [0, 92160)
// ---- phase-2 layout (aliases stage region; GEMM1 retired first) ----
#define OFF_H1   0         // 128 x 264 fp16 = 67584
#define OFF_D1S  67584     // 128 x 65 fp32 = 33280
#define OFF_B2   100864    // 2 stages x 10240
#define B2_STG   10240
// ---- persistent misc (above all stage regions) ----
#define OFF_ADJW 153600
#define OFF_ADJI 155392
#define OFF_DINV 157184
#define OFF_POOL 157440
#define SMEM_BYTES 158464

// ---- pre-converted operands (filled by prep kernels) ----
__device__ __half g_x[(size_t)BMAX * NNODE * DIM];
__device__ __half g_W1[C1 * DIM];
__device__ __half g_W2[C2 * C1];

__device__ __forceinline__ void mma_f16(float* c, const unsigned* a, const unsigned* b) {
    asm volatile(
        "mma.sync.aligned.m16n8k16.row.col.f32.f16.f16.f32 "
        "{%0,%1,%2,%3}, {%4,%5,%6,%7}, {%8,%9}, {%0,%1,%2,%3};\n"
        : "+f"(c[0]), "+f"(c[1]), "+f"(c[2]), "+f"(c[3])
        : "r"(a[0]), "r"(a[1]), "r"(a[2]), "r"(a[3]), "r"(b[0]), "r"(b[1]));
}
__device__ __forceinline__ void ldsm4(unsigned* r, uint32_t addr) {
    asm volatile("ldmatrix.sync.aligned.m8n8.x4.shared.b16 {%0,%1,%2,%3}, [%4];"
        : "=r"(r[0]), "=r"(r[1]), "=r"(r[2]), "=r"(r[3]) : "r"(addr));
}
__device__ __forceinline__ void cpa16(uint32_t dst, const void* src) {
    asm volatile("cp.async.cg.shared.global [%0], [%1], 16;" :: "r"(dst), "l"(src));
}
__device__ __forceinline__ void cpa16z(uint32_t dst, const void* src, int srcsize) {
    asm volatile("cp.async.cg.shared.global [%0], [%1], 16, %2;"
                 :: "r"(dst), "l"(src), "r"(srcsize));
}
#define CPA_COMMIT() asm volatile("cp.async.commit_group;" ::: "memory")
#define CPA_WAIT0()  asm volatile("cp.async.wait_group 0;" ::: "memory")
#define CPA_WAIT1()  asm volatile("cp.async.wait_group 1;" ::: "memory")

__device__ __forceinline__ unsigned packh(__half a, __half b) {
    return ((unsigned)__half_as_ushort(b) << 16) | (unsigned)__half_as_ushort(a);
}

// ==================== prep: x -> fp16 ====================
__global__ void prep_x(const float4* __restrict__ x4, int n4) {
    int i = blockIdx.x * blockDim.x + threadIdx.x;
    if (i >= n4) return;
    float4 v = x4[i];
    *(uint2*)(g_x + (size_t)i * 4) =
        make_uint2(packh(__float2half(v.x), __float2half(v.y)),
                   packh(__float2half(v.z), __float2half(v.w)));
}

// ==================== prep: convert + transpose weights ====================
__global__ void prep_weights(const float* __restrict__ W1, const float* __restrict__ W2) {
    int idx = blockIdx.x * blockDim.x + threadIdx.x;
    if (idx < C1 * DIM) {                       // W1 [768][256] -> [256][768]
        int k = idx >> 8, n = idx & 255;
        g_W1[n * DIM + k] = __float2half(W1[idx]);
    } else if (idx < C1 * DIM + C1 * C2) {      // W2 [256][128] -> [128][256]
        int j = idx - C1 * DIM;
        int k = j >> 7, n = j & 127;
        g_W2[n * C1 + k] = __float2half(W2[j]);
    }
}

// =========================== main fused kernel ===========================
__global__ void __launch_bounds__(TPB, 1)
gnn_fused(const float* __restrict__ b1, const float* __restrict__ b2,
          const float* __restrict__ Wf, const float* __restrict__ bf,
          float* __restrict__ out)
{
    extern __shared__ unsigned char smem[];
    const uint32_t sbase = (uint32_t)__cvta_generic_to_shared(smem);

    float* adjw   = (float*)(smem + OFF_ADJW);
    int*   adji   = (int*)(smem + OFF_ADJI);
    float* dinv   = (float*)(smem + OFF_DINV);
    float* pooled = (float*)(smem + OFF_POOL);
    float* d1s    = (float*)(smem + OFF_D1S);

    const int tid  = threadIdx.x;
    const int lane = tid & 31;
    const int wid  = tid >> 5;    // 0..15
    const int wm   = wid >> 2;    // 0..3  (m32 block)
    const int wn   = wid & 3;     // 0..3  (n64 G1 / n32 G2)
    const int tr   = lane >> 2;
    const int tc   = lane & 3;
    const int b0   = blockIdx.x * BT;

    // ldmatrix lane pattern
    const int lrow = (lane & 7) + ((lane >> 3) & 1) * 8;
    const int lkb  = (lane >> 4) * 16;

    // ---- adjacency (exact fp32) ----
    if (tid < NNODE) {
        int r = tid / 7, c = tid % 7;
        int nr = min(r + 1, 6) - max(r - 1, 0) + 1;
        int nc = min(c + 1, 6) - max(c - 1, 0) + 1;
        dinv[tid] = 1.0f / sqrtf((float)(nr * nc));
    }
    __syncthreads();
    if (tid < NNODE) {
        int r = tid / 7, c = tid % 7;
        float di = dinv[tid];
        int t = 0;
        for (int dr = -1; dr <= 1; dr++)
            for (int dc = -1; dc <= 1; dc++) {
                int rr = r + dr, cc = c + dc;
                if (rr >= 0 && rr < 7 && cc >= 0 && cc < 7) {
                    int j = rr * 7 + cc;
                    adji[tid * 9 + t] = j;
                    adjw[tid * 9 + t] = di * dinv[j];
                    t++;
                }
            }
        for (; t < 9; t++) { adji[tid * 9 + t] = 0; adjw[tid * 9 + t] = 0.0f; }
    }

    // ---- staging thread assignments (512 threads) ----
    // A: 128 rows x 4 chunks = 512 ops -> 1 per thread
    const int arow  = tid >> 2;
    const int ac    = tid & 3;
    const int ag    = arow >> 6;
    const int anode = arow & 63;
    const int asz   = (anode < NNODE) ? 16 : 0;
    const int anc   = min(anode, NNODE - 1);
    const __half* pxa = g_x + ((size_t)(b0 + ag) * NNODE + anc) * DIM + ac * 8;
    const uint32_t adst = (uint32_t)(arow * SROW + ac * 16);
    // B: 256 n x 4 chunks = 1024 ops -> 2 per thread
    const int bn  = tid >> 1;
    const int bc0 = (tid & 1) * 2;
    const __half* pw1 = g_W1 + (size_t)bn * DIM + bc0 * 8;
    const uint32_t bdst = (uint32_t)(B_T + bn * SROW + bc0 * 16);

    // frag base byte offsets
    const uint32_t aoff = (uint32_t)((wm * 32 + lrow) * SROW + lkb);
    const uint32_t boff = (uint32_t)((wn * 64 + lrow) * SROW + lkb);

    // ---- GEMM1 stage filler ----
    auto fill1 = [&](int kt, uint32_t stg) {
        const int ke = kt * 32;
        cpa16z(sbase + stg + A_T + adst, pxa + ke, asz);
        #pragma unroll
        for (int c = 0; c < 2; c++)
            cpa16(sbase + stg + bdst + c * 16, pw1 + ke + c * 8);
        CPA_COMMIT();
    };

    // ===== GEMM1: T1 = X @ W1  (128 x 256 x 768, fp16 single-pass) =====
    float acc[16][4];                 // warp tile m32 x n64
    #pragma unroll
    for (int j = 0; j < 16; j++)
        #pragma unroll
        for (int k = 0; k < 4; k++) acc[j][k] = 0.0f;

    fill1(0, 0);
    fill1(1, STG);

    #pragma unroll 1
    for (int kt = 0; kt < NST1; kt++) {
        const uint32_t cs = (uint32_t)(kt % 3) * STG;
        if (kt < NST1 - 2) CPA_WAIT1(); else CPA_WAIT0();
        __syncthreads();
        if (kt + 2 < NST1) fill1(kt + 2, (uint32_t)((kt + 2) % 3) * STG);

        #pragma unroll
        for (int kh = 0; kh < 2; kh++) {
            unsigned af[2][4];
            #pragma unroll
            for (int mi = 0; mi < 2; mi++)
                ldsm4(af[mi], sbase + cs + A_T + aoff + mi * 16 * SROW + kh * 32);
            #pragma unroll
            for (int p = 0; p < 4; p++) {
                unsigned bh4[4];
                ldsm4(bh4, sbase + cs + B_T + boff + p * 16 * SROW + kh * 32);
                #pragma unroll
                for (int h = 0; h < 2; h++) {
                    const int nj = p * 2 + h;
                    unsigned bh[2] = { bh4[h], bh4[2 + h] };
                    #pragma unroll
                    for (int mi = 0; mi < 2; mi++)
                        mma_f16(acc[mi*8+nj], af[mi], bh);
                }
            }
        }
    }
    __syncthreads();

    // GEMM2 B staging: 128 n x 4 chunks = 512 ops -> 1 per thread
    const int b2n = tid >> 2;
    const int b2c = tid & 3;
    const __half* pw2 = g_W2 + (size_t)b2n * C1 + b2c * 8;
    const uint32_t b2dst = (uint32_t)(b2n * SROW + b2c * 16);
    auto fill2 = [&](int kt, uint32_t stg) {
        cpa16(sbase + stg + b2dst, pw2 + kt * 32);
        CPA_COMMIT();
    };
    fill2(0, OFF_B2);       // latency absorbed by epilogue 1

    // ===== epilogue 1: H1 = fp16(relu(ADJ @ T1 + b1)) =====
    __half* H1 = (__half*)(smem + OFF_H1);
    #pragma unroll 1
    for (int ci = 0; ci < 4; ci++) {
        if (wn == ci) {
            #pragma unroll
            for (int mi = 0; mi < 2; mi++)
                #pragma unroll
                for (int nj = 0; nj < 8; nj++) {
                    const int row = wm*32 + mi*16 + tr;
                    const int col = nj*8 + tc*2;
                    float* a = acc[mi*8+nj];
                    d1s[row * DS + col]           = a[0];
                    d1s[row * DS + col + 1]       = a[1];
                    d1s[(row + 8) * DS + col]     = a[2];
                    d1s[(row + 8) * DS + col + 1] = a[3];
                }
        }
        __syncthreads();
        for (int task = tid; task < BT * NNODE * 64; task += TPB) {
            const int cl   = task & 63;
            const int rest = task >> 6;
            const int g    = (rest >= NNODE) ? 1 : 0;
            const int i    = rest - g * NNODE;
            float s = __ldg(&b1[ci * 64 + cl]);
            #pragma unroll
            for (int t = 0; t < 9; t++)
                s += adjw[i*9+t] * d1s[(g*64 + adji[i*9+t]) * DS + cl];
            s = fmaxf(s, 0.0f);
            H1[(g*64 + i) * SH + ci*64 + cl] = __float2half(s);
        }
        __syncthreads();
    }

    // ===== GEMM2: T2 = H1 @ W2  (128 x 128 x 256, fp16 single-pass) =====
    float acc2[8][4];                 // warp tile m32 x n32
    #pragma unroll
    for (int j = 0; j < 8; j++)
        #pragma unroll
        for (int k = 0; k < 4; k++) acc2[j][k] = 0.0f;

    const uint32_t hoff  = (uint32_t)((wm * 32 + lrow) * (SH * 2) + lkb);
    const uint32_t b2off = (uint32_t)((wn * 32 + lrow) * SROW + lkb);

    #pragma unroll 1
    for (int kt = 0; kt < NST2; kt++) {
        const uint32_t cs = OFF_B2 + (uint32_t)(kt & 1) * B2_STG;
        CPA_WAIT0();
        __syncthreads();
        if (kt + 1 < NST2) fill2(kt + 1, OFF_B2 + (uint32_t)((kt + 1) & 1) * B2_STG);

        #pragma unroll
        for (int kh = 0; kh < 2; kh++) {
            unsigned af[2][4];
            #pragma unroll
            for (int mi = 0; mi < 2; mi++)
                ldsm4(af[mi], sbase + OFF_H1 + hoff + mi*16*(SH*2) + kt*64 + kh*32);
            #pragma unroll
            for (int p = 0; p < 2; p++) {
                unsigned bh4[4];
                ldsm4(bh4, sbase + cs + b2off + p*16*SROW + kh*32);
                #pragma unroll
                for (int h = 0; h < 2; h++) {
                    const int nj = p*2 + h;
                    unsigned bh[2] = { bh4[h], bh4[2+h] };
                    #pragma unroll
                    for (int mi = 0; mi < 2; mi++)
                        mma_f16(acc2[mi*4+nj], af[mi], bh);
                }
            }
        }
    }
    __syncthreads();

    // ======== epilogue 2: ADJ + bias + relu + mean-pool + head ========
    #pragma unroll 1
    for (int ci = 0; ci < 2; ci++) {
        if ((wn >> 1) == ci) {
            #pragma unroll
            for (int mi = 0; mi < 2; mi++)
                #pragma unroll
                for (int nj = 0; nj < 4; nj++) {
                    const int row = wm*32 + mi*16 + tr;
                    const int col = (wn & 1)*32 + nj*8 + tc*2;
                    float* a = acc2[mi*4+nj];
                    d1s[row * DS + col]           = a[0];
                    d1s[row * DS + col + 1]       = a[1];
                    d1s[(row + 8) * DS + col]     = a[2];
                    d1s[(row + 8) * DS + col + 1] = a[3];
                }
        }
        __syncthreads();
        {
            const int quarter = tid & 3;
            const int rest    = tid >> 2;       // 0..127
            const int g       = rest >> 6;
            const int cl      = rest & 63;
            const float bias  = __ldg(&b2[ci * 64 + cl]);
            const int i0   = quarter * 13;
            const int icnt = (quarter < 3) ? 13 : 10;
            float ps = 0.0f;
            for (int ii = 0; ii < icnt; ii++) {
                const int i = i0 + ii;
                float s = bias;
                #pragma unroll
                for (int t = 0; t < 9; t++)
                    s += adjw[i*9+t] * d1s[(g*64 + adji[i*9+t]) * DS + cl];
                ps += fmaxf(s, 0.0f);
            }
            ps += __shfl_xor_sync(0xFFFFFFFFu, ps, 1);
            ps += __shfl_xor_sync(0xFFFFFFFFu, ps, 2);
            if (quarter == 0) pooled[g * C2 + ci * 64 + cl] = ps * (1.0f / 49.0f);
        }
        __syncthreads();
    }

    if (tid < BT * NCLS) {
        const int g = tid / NCLS, o = tid - g * NCLS;
        float s = __ldg(&bf[o]);
        const float* pp = pooled + g * C2;
        #pragma unroll 8
        for (int k = 0; k < C2; k++) s += pp[k] * __ldg(&Wf[k * NCLS + o]);
        out[(size_t)(b0 + g) * NCLS + o] = s;
    }
}

extern "C" void kernel_launch(void* const* d_in, const int* in_sizes, int n_in,
                              void* d_out, int out_size)
{
    const float* x  = (const float*)d_in[0];
    const float* W1 = (const float*)d_in[1];
    const float* b1 = (const float*)d_in[2];
    const float* W2 = (const float*)d_in[3];
    const float* b2 = (const float*)d_in[4];
    const float* Wf = (const float*)d_in[5];
    const float* bf = (const float*)d_in[6];
    float* out = (float*)d_out;

    const int B  = in_sizes[0] / (NNODE * DIM);   // 4096
    const int n4 = in_sizes[0] / 4;

    prep_x<<<(n4 + 255) / 256, 256>>>((const float4*)x, n4);
    prep_weights<<<(C1 * DIM + C1 * C2 + 255) / 256, 256>>>(W1, W2);

    cudaFuncSetAttribute(gnn_fused, cudaFuncAttributeMaxDynamicSharedMemorySize, SMEM_BYTES);
    gnn_fused<<<B / BT, TPB, SMEM_BYTES>>>(b1, b2, Wf, bf, out);
}

// round 14
// speedup vs baseline: 2.2576x; 1.1630x over previous
#include <cuda_runtime.h>
#include <cuda_fp16.h>
#include <stdint.h>

#define TPB   512
#define NNODE 49
#define BT    2
#define DIM   768
#define C1    256
#define C2    128
#define NCLS  13
#define NST1  24           // 768/32 K32 stages
#define NST2  8            // 256/32

#define SROW 80            // stage tile row stride bytes -> conflict-free LDSM
#define SH   264           // H1 row stride (fp16 elems) = 528B
#define DS2  130           // d1s fp32 row stride (128 cols + pad)

// ---- GEMM1 stage layout (bytes within stage) ----
#define A_T  0             // 128 x 80 (fp16)
#define B_T  10240         // 256 x 80 (fp16)
#define STG  30720         // x3 stages: [0, 92160)
// ---- phase-2 layout (aliases stage region; GEMM1 retired first) ----
#define OFF_H1   0         // 128 x 264 fp16 = 67584
#define OFF_D1S  67584     // 128 x 130 fp32 = 66560
#define OFF_B2   134144    // 2 stages x 10240 -> ends 154624
#define B2_STG   10240
// ---- persistent misc (above all aliased regions) ----
#define OFF_ADJW 154624
#define OFF_ADJI 156416
#define OFF_DINV 158208
#define OFF_POOL 158464
#define SMEM_BYTES 159488

// ---- pre-converted weights (filled by prep kernel) ----
__device__ __half g_W1[C1 * DIM];
__device__ __half g_W2[C2 * C1];

__device__ __forceinline__ void mma_f16(float* c, const unsigned* a, const unsigned* b) {
    asm volatile(
        "mma.sync.aligned.m16n8k16.row.col.f32.f16.f16.f32 "
        "{%0,%1,%2,%3}, {%4,%5,%6,%7}, {%8,%9}, {%0,%1,%2,%3};\n"
        : "+f"(c[0]), "+f"(c[1]), "+f"(c[2]), "+f"(c[3])
        : "r"(a[0]), "r"(a[1]), "r"(a[2]), "r"(a[3]), "r"(b[0]), "r"(b[1]));
}
__device__ __forceinline__ void ldsm4(unsigned* r, uint32_t addr) {
    asm volatile("ldmatrix.sync.aligned.m8n8.x4.shared.b16 {%0,%1,%2,%3}, [%4];"
        : "=r"(r[0]), "=r"(r[1]), "=r"(r[2]), "=r"(r[3]) : "r"(addr));
}
__device__ __forceinline__ void cpa16(uint32_t dst, const void* src) {
    asm volatile("cp.async.cg.shared.global [%0], [%1], 16;" :: "r"(dst), "l"(src));
}
#define CPA_COMMIT() asm volatile("cp.async.commit_group;" ::: "memory")
#define CPA_WAIT0()  asm volatile("cp.async.wait_group 0;" ::: "memory")
#define CPA_WAIT1()  asm volatile("cp.async.wait_group 1;" ::: "memory")

__device__ __forceinline__ unsigned packh(__half a, __half b) {
    return ((unsigned)__half_as_ushort(b) << 16) | (unsigned)__half_as_ushort(a);
}

// ==================== prep: convert + transpose weights ====================
__global__ void prep_weights(const float* __restrict__ W1, const float* __restrict__ W2) {
    int idx = blockIdx.x * blockDim.x + threadIdx.x;
    if (idx < C1 * DIM) {                       // W1 [768][256] -> [256][768]
        int k = idx >> 8, n = idx & 255;
        g_W1[n * DIM + k] = __float2half(W1[idx]);
    } else if (idx < C1 * DIM + C1 * C2) {      // W2 [256][128] -> [128][256]
        int j = idx - C1 * DIM;
        int k = j >> 7, n = j & 127;
        g_W2[n * C1 + k] = __float2half(W2[j]);
    }
}

// =========================== main fused kernel ===========================
__global__ void __launch_bounds__(TPB, 1)
gnn_fused(const float* __restrict__ x,  const float* __restrict__ b1,
          const float* __restrict__ b2, const float* __restrict__ Wf,
          const float* __restrict__ bf, float* __restrict__ out)
{
    extern __shared__ unsigned char smem[];
    const uint32_t sbase = (uint32_t)__cvta_generic_to_shared(smem);

    float* adjw   = (float*)(smem + OFF_ADJW);
    int*   adji   = (int*)(smem + OFF_ADJI);
    float* dinv   = (float*)(smem + OFF_DINV);
    float* pooled = (float*)(smem + OFF_POOL);
    float* d1s    = (float*)(smem + OFF_D1S);

    const int tid  = threadIdx.x;
    const int lane = tid & 31;
    const int wid  = tid >> 5;    // 0..15
    const int wm   = wid >> 2;    // 0..3  (m32 block)
    const int wn   = wid & 3;     // 0..3  (n64 G1 / n32 G2)
    const int tr   = lane >> 2;
    const int tc   = lane & 3;
    const int b0   = blockIdx.x * BT;

    // ldmatrix lane pattern
    const int lrow = (lane & 7) + ((lane >> 3) & 1) * 8;
    const int lkb  = (lane >> 4) * 16;

    // ---- adjacency (exact fp32) ----
    if (tid < NNODE) {
        int r = tid / 7, c = tid % 7;
        int nr = min(r + 1, 6) - max(r - 1, 0) + 1;
        int nc = min(c + 1, 6) - max(c - 1, 0) + 1;
        dinv[tid] = 1.0f / sqrtf((float)(nr * nc));
    }
    __syncthreads();
    if (tid < NNODE) {
        int r = tid / 7, c = tid % 7;
        float di = dinv[tid];
        int t = 0;
        for (int dr = -1; dr <= 1; dr++)
            for (int dc = -1; dc <= 1; dc++) {
                int rr = r + dr, cc = c + dc;
                if (rr >= 0 && rr < 7 && cc >= 0 && cc < 7) {
                    int j = rr * 7 + cc;
                    adji[tid * 9 + t] = j;
                    adjw[tid * 9 + t] = di * dinv[j];
                    t++;
                }
            }
        for (; t < 9; t++) { adji[tid * 9 + t] = 0; adjw[tid * 9 + t] = 0.0f; }
    }

    // ---- staging thread assignments (512 threads) ----
    // A: 128 rows x 4 col-chunks (8 fp32 each) -> 1 per thread; LDG fp32 + cvt + STS.128
    const int arow  = tid >> 2;
    const int ac    = tid & 3;
    const int ag    = arow >> 6;
    const int anode = arow & 63;
    const bool aval = (anode < NNODE);
    const float* pxa = x + ((size_t)(b0 + ag) * NNODE + min(anode, NNODE - 1)) * DIM + ac * 8;
    const uint32_t adst = (uint32_t)(arow * SROW + ac * 16);
    // B: 256 n x 4 chunks = 1024 cp.async -> 2 per thread
    const int bn  = tid >> 1;
    const int bc0 = (tid & 1) * 2;
    const __half* pw1 = g_W1 + (size_t)bn * DIM + bc0 * 8;
    const uint32_t bdst = (uint32_t)(B_T + bn * SROW + bc0 * 16);

    // frag base byte offsets
    const uint32_t aoff = (uint32_t)((wm * 32 + lrow) * SROW + lkb);
    const uint32_t boff = (uint32_t)((wn * 64 + lrow) * SROW + lkb);

    // ---- stage helpers ----
    auto ldA = [&](int kt, float4* r) {
        if (aval) {
            r[0] = *(const float4*)(pxa + kt * 32);
            r[1] = *(const float4*)(pxa + kt * 32 + 4);
        } else {
            r[0] = make_float4(0.f, 0.f, 0.f, 0.f);
            r[1] = make_float4(0.f, 0.f, 0.f, 0.f);
        }
    };
    auto stsA = [&](uint32_t stg, const float4* r) {
        uint4 v;
        v.x = packh(__float2half(r[0].x), __float2half(r[0].y));
        v.y = packh(__float2half(r[0].z), __float2half(r[0].w));
        v.z = packh(__float2half(r[1].x), __float2half(r[1].y));
        v.w = packh(__float2half(r[1].z), __float2half(r[1].w));
        asm volatile("st.shared.v4.b32 [%0], {%1,%2,%3,%4};"
                     :: "r"(sbase + stg + A_T + adst),
                        "r"(v.x), "r"(v.y), "r"(v.z), "r"(v.w) : "memory");
    };
    auto fillB = [&](int kt, uint32_t stg) {
        const int ke = kt * 32;
        #pragma unroll
        for (int c = 0; c < 2; c++)
            cpa16(sbase + stg + bdst + c * 16, pw1 + ke + c * 8);
        CPA_COMMIT();
    };

    // ===== GEMM1: T1 = X @ W1  (128 x 256 x 768, fp16 single-pass) =====
    float acc[16][4];                 // warp tile m32 x n64
    #pragma unroll
    for (int j = 0; j < 16; j++)
        #pragma unroll
        for (int k = 0; k < 4; k++) acc[j][k] = 0.0f;

    {
        float4 r0[2], r1[2];
        ldA(0, r0); ldA(1, r1);
        stsA(0, r0); stsA(STG, r1);
        fillB(0, 0); fillB(1, STG);
    }
    float4 rP[2];
    ldA(2, rP);

    #pragma unroll 1
    for (int kt = 0; kt < NST1; kt++) {
        const uint32_t cs = (uint32_t)(kt % 3) * STG;
        if (kt < NST1 - 2) CPA_WAIT1(); else CPA_WAIT0();
        __syncthreads();
        if (kt + 2 < NST1) {
            const uint32_t ns = (uint32_t)((kt + 2) % 3) * STG;
            stsA(ns, rP);
            fillB(kt + 2, ns);
            if (kt + 3 < NST1) ldA(kt + 3, rP);
        }

        #pragma unroll
        for (int kh = 0; kh < 2; kh++) {
            unsigned af[2][4];
            #pragma unroll
            for (int mi = 0; mi < 2; mi++)
                ldsm4(af[mi], sbase + cs + A_T + aoff + mi * 16 * SROW + kh * 32);
            #pragma unroll
            for (int p = 0; p < 4; p++) {
                unsigned bh4[4];
                ldsm4(bh4, sbase + cs + B_T + boff + p * 16 * SROW + kh * 32);
                #pragma unroll
                for (int h = 0; h < 2; h++) {
                    const int nj = p * 2 + h;
                    unsigned bh[2] = { bh4[h], bh4[2 + h] };
                    #pragma unroll
                    for (int mi = 0; mi < 2; mi++)
                        mma_f16(acc[mi*8+nj], af[mi], bh);
                }
            }
        }
    }
    __syncthreads();

    // GEMM2 B staging: 128 n x 4 chunks = 512 ops -> 1 per thread
    const int b2n = tid >> 2;
    const int b2c = tid & 3;
    const __half* pw2 = g_W2 + (size_t)b2n * C1 + b2c * 8;
    const uint32_t b2dst = (uint32_t)(b2n * SROW + b2c * 16);
    auto fill2 = [&](int kt, uint32_t stg) {
        cpa16(sbase + stg + b2dst, pw2 + kt * 32);
        CPA_COMMIT();
    };
    fill2(0, OFF_B2);       // latency absorbed by epilogue 1

    // ===== epilogue 1 (2 chunks of 128 cols): H1 = fp16(relu(ADJ @ T1 + b1)) =====
    __half* H1 = (__half*)(smem + OFF_H1);
    #pragma unroll 1
    for (int ci = 0; ci < 2; ci++) {
        if ((wn >> 1) == ci) {
            #pragma unroll
            for (int mi = 0; mi < 2; mi++)
                #pragma unroll
                for (int nj = 0; nj < 8; nj++) {
                    const int row = wm*32 + mi*16 + tr;
                    const int col = (wn & 1)*64 + nj*8 + tc*2;
                    float* a = acc[mi*8+nj];
                    d1s[row * DS2 + col]           = a[0];
                    d1s[row * DS2 + col + 1]       = a[1];
                    d1s[(row + 8) * DS2 + col]     = a[2];
                    d1s[(row + 8) * DS2 + col + 1] = a[3];
                }
        }
        __syncthreads();
        for (int task = tid; task < BT * NNODE * 128; task += TPB) {
            const int cl   = task & 127;
            const int rest = task >> 7;
            const int g    = (rest >= NNODE) ? 1 : 0;
            const int i    = rest - g * NNODE;
            float s = __ldg(&b1[ci * 128 + cl]);
            #pragma unroll
            for (int t = 0; t < 9; t++)
                s += adjw[i*9+t] * d1s[(g*64 + adji[i*9+t]) * DS2 + cl];
            s = fmaxf(s, 0.0f);
            H1[(g*64 + i) * SH + ci*128 + cl] = __float2half(s);
        }
        __syncthreads();
    }

    // ===== GEMM2: T2 = H1 @ W2  (128 x 128 x 256, fp16 single-pass) =====
    float acc2[8][4];                 // warp tile m32 x n32
    #pragma unroll
    for (int j = 0; j < 8; j++)
        #pragma unroll
        for (int k = 0; k < 4; k++) acc2[j][k] = 0.0f;

    const uint32_t hoff  = (uint32_t)((wm * 32 + lrow) * (SH * 2) + lkb);
    const uint32_t b2off = (uint32_t)((wn * 32 + lrow) * SROW + lkb);

    #pragma unroll 1
    for (int kt = 0; kt < NST2; kt++) {
        const uint32_t cs = OFF_B2 + (uint32_t)(kt & 1) * B2_STG;
        CPA_WAIT0();
        __syncthreads();
        if (kt + 1 < NST2) fill2(kt + 1, OFF_B2 + (uint32_t)((kt + 1) & 1) * B2_STG);

        #pragma unroll
        for (int kh = 0; kh < 2; kh++) {
            unsigned af[2][4];
            #pragma unroll
            for (int mi = 0; mi < 2; mi++)
                ldsm4(af[mi], sbase + OFF_H1 + hoff + mi*16*(SH*2) + kt*64 + kh*32);
            #pragma unroll
            for (int p = 0; p < 2; p++) {
                unsigned bh4[4];
                ldsm4(bh4, sbase + cs + b2off + p*16*SROW + kh*32);
                #pragma unroll
                for (int h = 0; h < 2; h++) {
                    const int nj = p*2 + h;
                    unsigned bh[2] = { bh4[h], bh4[2+h] };
                    #pragma unroll
                    for (int mi = 0; mi < 2; mi++)
                        mma_f16(acc2[mi*4+nj], af[mi], bh);
                }
            }
        }
    }
    __syncthreads();

    // ======== epilogue 2 (single 128-col pass): ADJ + bias + relu + pool + head ========
    {
        #pragma unroll
        for (int mi = 0; mi < 2; mi++)
            #pragma unroll
            for (int nj = 0; nj < 4; nj++) {
                const int row = wm*32 + mi*16 + tr;
                const int col = wn*32 + nj*8 + tc*2;
                float* a = acc2[mi*4+nj];
                d1s[row * DS2 + col]           = a[0];
                d1s[row * DS2 + col + 1]       = a[1];
                d1s[(row + 8) * DS2 + col]     = a[2];
                d1s[(row + 8) * DS2 + col + 1] = a[3];
            }
    }
    __syncthreads();
    {
        const int half = tid & 1;
        const int rest = tid >> 1;          // 0..255
        const int g    = rest >> 7;
        const int cl   = rest & 127;
        const float bias = __ldg(&b2[cl]);
        const int i0   = half * 25;
        const int icnt = half ? 24 : 25;
        float ps = 0.0f;
        for (int ii = 0; ii < icnt; ii++) {
            const int i = i0 + ii;
            float s = bias;
            #pragma unroll
            for (int t = 0; t < 9; t++)
                s += adjw[i*9+t] * d1s[(g*64 + adji[i*9+t]) * DS2 + cl];
            ps += fmaxf(s, 0.0f);
        }
        ps += __shfl_xor_sync(0xFFFFFFFFu, ps, 1);
        if (half == 0) pooled[g * C2 + cl] = ps * (1.0f / 49.0f);
    }
    __syncthreads();

    if (tid < BT * NCLS) {
        const int g = tid / NCLS, o = tid - g * NCLS;
        float s = __ldg(&bf[o]);
        const float* pp = pooled + g * C2;
        #pragma unroll 8
        for (int k = 0; k < C2; k++) s += pp[k] * __ldg(&Wf[k * NCLS + o]);
        out[(size_t)(b0 + g) * NCLS + o] = s;
    }
}

extern "C" void kernel_launch(void* const* d_in, const int* in_sizes, int n_in,
                              void* d_out, int out_size)
{
    const float* x  = (const float*)d_in[0];
    const float* W1 = (const float*)d_in[1];
    const float* b1 = (const float*)d_in[2];
    const float* W2 = (const float*)d_in[3];
    const float* b2 = (const float*)d_in[4];
    const float* Wf = (const float*)d_in[5];
    const float* bf = (const float*)d_in[6];
    float* out = (float*)d_out;

    const int B = in_sizes[0] / (NNODE * DIM);   // 4096

    prep_weights<<<(C1 * DIM + C1 * C2 + 255) / 256, 256>>>(W1, W2);

    cudaFuncSetAttribute(gnn_fused, cudaFuncAttributeMaxDynamicSharedMemorySize, SMEM_BYTES);
    gnn_fused<<<B / BT, TPB, SMEM_BYTES>>>(x, b1, b2, Wf, bf, out);
}

// round 15
// speedup vs baseline: 2.4537x; 1.0868x over previous
#include <cuda_runtime.h>
#include <cuda_fp16.h>
#include <stdint.h>

#define TPB   512
#define NNODE 49
#define BT    2
#define DIM   768
#define C1    256
#define C2    128
#define NCLS  13
#define NST1  24           // 768/32 K32 stages
#define NST2  8            // 256/32

#define SROW 80            // stage tile row stride bytes -> conflict-free LDSM
#define SH   264           // H1 row stride (fp16 elems) = 528B
#define DSH  136           // d1s half row stride (128 cols + pad)

// ---- GEMM1 stage layout (bytes within stage) ----
#define A_T  0             // 128 x 80 (fp16)
#define B_T  10240         // 256 x 80 (fp16)
#define STG  30720         // x4 stages: [0, 122880)
// ---- phase-2 layout (aliases stage region; GEMM1 retired first) ----
#define OFF_H1   0         // 128 x 264 fp16 = 67584
#define OFF_D1S  67584     // 128 x 136 fp16 = 34816
#define OFF_B2   102400    // 4 stages x 10240 -> ends 143360
#define B2_STG   10240
// ---- persistent misc (above all aliased regions) ----
#define OFF_ADJW 143360
#define OFF_ADJI 145152
#define OFF_DINV 146944
#define OFF_POOL 147200
#define SMEM_BYTES 148480

// ---- pre-converted weights (filled by prep kernel) ----
__device__ __half g_W1[C1 * DIM];
__device__ __half g_W2[C2 * C1];

__device__ __forceinline__ void mma_f16(float* c, const unsigned* a, const unsigned* b) {
    asm volatile(
        "mma.sync.aligned.m16n8k16.row.col.f32.f16.f16.f32 "
        "{%0,%1,%2,%3}, {%4,%5,%6,%7}, {%8,%9}, {%0,%1,%2,%3};\n"
        : "+f"(c[0]), "+f"(c[1]), "+f"(c[2]), "+f"(c[3])
        : "r"(a[0]), "r"(a[1]), "r"(a[2]), "r"(a[3]), "r"(b[0]), "r"(b[1]));
}
__device__ __forceinline__ void ldsm4(unsigned* r, uint32_t addr) {
    asm volatile("ldmatrix.sync.aligned.m8n8.x4.shared.b16 {%0,%1,%2,%3}, [%4];"
        : "=r"(r[0]), "=r"(r[1]), "=r"(r[2]), "=r"(r[3]) : "r"(addr));
}
__device__ __forceinline__ void cpa16(uint32_t dst, const void* src) {
    asm volatile("cp.async.cg.shared.global [%0], [%1], 16;" :: "r"(dst), "l"(src));
}
#define CPA_COMMIT() asm volatile("cp.async.commit_group;" ::: "memory")
#define CPA_WAIT0()  asm volatile("cp.async.wait_group 0;" ::: "memory")

__device__ __forceinline__ unsigned packh(__half a, __half b) {
    return ((unsigned)__half_as_ushort(b) << 16) | (unsigned)__half_as_ushort(a);
}
__device__ __forceinline__ unsigned packf(float a, float b) {
    return packh(__float2half(a), __float2half(b));
}
__device__ __forceinline__ float2 h2f(unsigned v) {
    __half2 h = *(__half2*)&v;
    return __half22float2(h);
}

// ==================== prep: convert + transpose weights ====================
__global__ void prep_weights(const float* __restrict__ W1, const float* __restrict__ W2) {
    int idx = blockIdx.x * blockDim.x + threadIdx.x;
    if (idx < C1 * DIM) {                       // W1 [768][256] -> [256][768]
        int k = idx >> 8, n = idx & 255;
        g_W1[n * DIM + k] = __float2half(W1[idx]);
    } else if (idx < C1 * DIM + C1 * C2) {      // W2 [256][128] -> [128][256]
        int j = idx - C1 * DIM;
        int k = j >> 7, n = j & 127;
        g_W2[n * C1 + k] = __float2half(W2[j]);
    }
}

// =========================== main fused kernel ===========================
__global__ void __launch_bounds__(TPB, 1)
gnn_fused(const float* __restrict__ x,  const float* __restrict__ b1,
          const float* __restrict__ b2, const float* __restrict__ Wf,
          const float* __restrict__ bf, float* __restrict__ out)
{
    extern __shared__ unsigned char smem[];
    const uint32_t sbase = (uint32_t)__cvta_generic_to_shared(smem);

    float* adjw   = (float*)(smem + OFF_ADJW);
    int*   adji   = (int*)(smem + OFF_ADJI);
    float* dinv   = (float*)(smem + OFF_DINV);
    float* pooled = (float*)(smem + OFF_POOL);
    __half* d1h   = (__half*)(smem + OFF_D1S);

    const int tid  = threadIdx.x;
    const int lane = tid & 31;
    const int wid  = tid >> 5;    // 0..15
    const int wm   = wid >> 2;    // 0..3  (m32 block)
    const int wn   = wid & 3;     // 0..3  (n64 G1 / n32 G2)
    const int tr   = lane >> 2;
    const int tc   = lane & 3;
    const int b0   = blockIdx.x * BT;

    // ldmatrix lane pattern
    const int lrow = (lane & 7) + ((lane >> 3) & 1) * 8;
    const int lkb  = (lane >> 4) * 16;

    // ---- adjacency (exact fp32) ----
    if (tid < NNODE) {
        int r = tid / 7, c = tid % 7;
        int nr = min(r + 1, 6) - max(r - 1, 0) + 1;
        int nc = min(c + 1, 6) - max(c - 1, 0) + 1;
        dinv[tid] = 1.0f / sqrtf((float)(nr * nc));
    }
    __syncthreads();
    if (tid < NNODE) {
        int r = tid / 7, c = tid % 7;
        float di = dinv[tid];
        int t = 0;
        for (int dr = -1; dr <= 1; dr++)
            for (int dc = -1; dc <= 1; dc++) {
                int rr = r + dr, cc = c + dc;
                if (rr >= 0 && rr < 7 && cc >= 0 && cc < 7) {
                    int j = rr * 7 + cc;
                    adji[tid * 9 + t] = j;
                    adjw[tid * 9 + t] = di * dinv[j];
                    t++;
                }
            }
        for (; t < 9; t++) { adji[tid * 9 + t] = 0; adjw[tid * 9 + t] = 0.0f; }
    }

    // ---- staging thread assignments (512 threads) ----
    const int arow  = tid >> 2;
    const int ac    = tid & 3;
    const int ag    = arow >> 6;
    const int anode = arow & 63;
    const bool aval = (anode < NNODE);
    const float* pxa = x + ((size_t)(b0 + ag) * NNODE + min(anode, NNODE - 1)) * DIM + ac * 8;
    const uint32_t adst = (uint32_t)(arow * SROW + ac * 16);
    const int bn  = tid >> 1;
    const int bc0 = (tid & 1) * 2;
    const __half* pw1 = g_W1 + (size_t)bn * DIM + bc0 * 8;
    const uint32_t bdst = (uint32_t)(B_T + bn * SROW + bc0 * 16);

    // frag base byte offsets
    const uint32_t aoff = (uint32_t)((wm * 32 + lrow) * SROW + lkb);
    const uint32_t boff = (uint32_t)((wn * 64 + lrow) * SROW + lkb);

    // ---- stage helpers ----
    auto ldA = [&](int kt, uint4& r) {
        if (aval) {
            float4 a = *(const float4*)(pxa + kt * 32);
            float4 b = *(const float4*)(pxa + kt * 32 + 4);
            r.x = packf(a.x, a.y); r.y = packf(a.z, a.w);
            r.z = packf(b.x, b.y); r.w = packf(b.z, b.w);
        } else r = make_uint4(0, 0, 0, 0);
    };
    auto stsA = [&](uint32_t stg, const uint4& v) {
        asm volatile("st.shared.v4.b32 [%0], {%1,%2,%3,%4};"
                     :: "r"(sbase + stg + A_T + adst),
                        "r"(v.x), "r"(v.y), "r"(v.z), "r"(v.w) : "memory");
    };
    auto fillB = [&](int kt, uint32_t stg) {
        const int ke = kt * 32;
        #pragma unroll
        for (int c = 0; c < 2; c++)
            cpa16(sbase + stg + bdst + c * 16, pw1 + ke + c * 8);
        CPA_COMMIT();
    };

    // ===== GEMM1: T1 = X @ W1  (128 x 256 x 768, fp16, pair-stage) =====
    float acc[16][4];
    #pragma unroll
    for (int j = 0; j < 16; j++)
        #pragma unroll
        for (int k = 0; k < 4; k++) acc[j][k] = 0.0f;

    auto compute1 = [&](int kt) {
        const uint32_t cs = (uint32_t)(kt & 3) * STG;
        #pragma unroll
        for (int kh = 0; kh < 2; kh++) {
            unsigned af[2][4];
            #pragma unroll
            for (int mi = 0; mi < 2; mi++)
                ldsm4(af[mi], sbase + cs + A_T + aoff + mi * 16 * SROW + kh * 32);
            #pragma unroll
            for (int p = 0; p < 4; p++) {
                unsigned bh4[4];
                ldsm4(bh4, sbase + cs + B_T + boff + p * 16 * SROW + kh * 32);
                #pragma unroll
                for (int h = 0; h < 2; h++) {
                    const int nj = p * 2 + h;
                    unsigned bh[2] = { bh4[h], bh4[2 + h] };
                    #pragma unroll
                    for (int mi = 0; mi < 2; mi++)
                        mma_f16(acc[mi*8+nj], af[mi], bh);
                }
            }
        }
    };

    // prologue: fill stages 0,1; prefetch A for 2,3 into regs
    uint4 rP0, rP1;
    {
        uint4 t0, t1;
        ldA(0, t0); ldA(1, t1);
        stsA(0, t0); stsA(STG, t1);
        fillB(0, 0); fillB(1, STG);
        ldA(2, rP0); ldA(3, rP1);
    }

    #pragma unroll 1
    for (int kt = 0; kt < NST1; kt += 2) {
        CPA_WAIT0();
        __syncthreads();
        if (kt + 2 < NST1) {
            const uint32_t n0 = (uint32_t)((kt + 2) & 3) * STG;
            const uint32_t n1 = (uint32_t)((kt + 3) & 3) * STG;
            stsA(n0, rP0); fillB(kt + 2, n0);
            stsA(n1, rP1); fillB(kt + 3, n1);
            if (kt + 4 < NST1) { ldA(kt + 4, rP0); ldA(kt + 5, rP1); }
        }
        compute1(kt);
        compute1(kt + 1);
    }
    __syncthreads();

    // GEMM2 B staging: 128 n x 4 chunks = 512 ops -> 1 per thread
    const int b2n = tid >> 2;
    const int b2c = tid & 3;
    const __half* pw2 = g_W2 + (size_t)b2n * C1 + b2c * 8;
    const uint32_t b2dst = (uint32_t)(b2n * SROW + b2c * 16);
    auto fill2 = [&](int kt) {
        cpa16(sbase + OFF_B2 + (uint32_t)(kt & 3) * B2_STG + b2dst, pw2 + kt * 32);
        CPA_COMMIT();
    };
    fill2(0); fill2(1);     // latency absorbed by epilogue 1

    // ===== epilogue 1 (2 chunks, half scratch): H1 = fp16(relu(ADJ@T1 + b1)) =====
    __half* H1 = (__half*)(smem + OFF_H1);
    #pragma unroll 1
    for (int ci = 0; ci < 2; ci++) {
        if ((wn >> 1) == ci) {
            #pragma unroll
            for (int mi = 0; mi < 2; mi++)
                #pragma unroll
                for (int nj = 0; nj < 8; nj++) {
                    const int row = wm*32 + mi*16 + tr;
                    const int col = (wn & 1)*64 + nj*8 + tc*2;
                    float* a = acc[mi*8+nj];
                    *(unsigned*)(d1h + row * DSH + col)       = packf(a[0], a[1]);
                    *(unsigned*)(d1h + (row + 8) * DSH + col) = packf(a[2], a[3]);
                }
        }
        __syncthreads();
        for (int task = tid; task < BT * NNODE * 64; task += TPB) {
            const int cl2  = task & 63;
            const int rest = task >> 6;
            const int g    = (rest >= NNODE) ? 1 : 0;
            const int i    = rest - g * NNODE;
            float2 s = __ldg((const float2*)(b1 + ci * 128 + cl2 * 2));
            #pragma unroll
            for (int t = 0; t < 9; t++) {
                const float w = adjw[i*9+t];
                float2 v = h2f(*(unsigned*)(d1h + (g*64 + adji[i*9+t]) * DSH + cl2*2));
                s.x += w * v.x;
                s.y += w * v.y;
            }
            s.x = fmaxf(s.x, 0.0f);
            s.y = fmaxf(s.y, 0.0f);
            *(unsigned*)(H1 + (g*64 + i) * SH + ci*128 + cl2*2) = packf(s.x, s.y);
        }
        __syncthreads();
    }

    // ===== GEMM2: T2 = H1 @ W2  (128 x 128 x 256, fp16, pair-stage) =====
    float acc2[8][4];
    #pragma unroll
    for (int j = 0; j < 8; j++)
        #pragma unroll
        for (int k = 0; k < 4; k++) acc2[j][k] = 0.0f;

    const uint32_t hoff  = (uint32_t)((wm * 32 + lrow) * (SH * 2) + lkb);
    const uint32_t b2off = (uint32_t)((wn * 32 + lrow) * SROW + lkb);

    auto compute2 = [&](int kt) {
        const uint32_t cs = OFF_B2 + (uint32_t)(kt & 3) * B2_STG;
        #pragma unroll
        for (int kh = 0; kh < 2; kh++) {
            unsigned af[2][4];
            #pragma unroll
            for (int mi = 0; mi < 2; mi++)
                ldsm4(af[mi], sbase + OFF_H1 + hoff + mi*16*(SH*2) + kt*64 + kh*32);
            #pragma unroll
            for (int p = 0; p < 2; p++) {
                unsigned bh4[4];
                ldsm4(bh4, sbase + cs + b2off + p*16*SROW + kh*32);
                #pragma unroll
                for (int h = 0; h < 2; h++) {
                    const int nj = p*2 + h;
                    unsigned bh[2] = { bh4[h], bh4[2+h] };
                    #pragma unroll
                    for (int mi = 0; mi < 2; mi++)
                        mma_f16(acc2[mi*4+nj], af[mi], bh);
                }
            }
        }
    };

    #pragma unroll 1
    for (int kt = 0; kt < NST2; kt += 2) {
        CPA_WAIT0();
        __syncthreads();
        if (kt + 2 < NST2) { fill2(kt + 2); fill2(kt + 3); }
        compute2(kt);
        compute2(kt + 1);
    }
    __syncthreads();

    // ======== epilogue 2 (half scratch): ADJ + bias + relu + pool + head ========
    {
        #pragma unroll
        for (int mi = 0; mi < 2; mi++)
            #pragma unroll
            for (int nj = 0; nj < 4; nj++) {
                const int row = wm*32 + mi*16 + tr;
                const int col = wn*32 + nj*8 + tc*2;
                float* a = acc2[mi*4+nj];
                *(unsigned*)(d1h + row * DSH + col)       = packf(a[0], a[1]);
                *(unsigned*)(d1h + (row + 8) * DSH + col) = packf(a[2], a[3]);
            }
    }
    __syncthreads();
    {
        const int quarter = tid & 3;
        const int rest    = tid >> 2;       // 0..127
        const int g       = rest >> 6;
        const int cl2     = rest & 63;
        float2 bias = __ldg((const float2*)(b2 + cl2 * 2));
        const int i0   = quarter * 13;
        const int icnt = (quarter < 3) ? 13 : 10;
        float2 ps = make_float2(0.0f, 0.0f);
        for (int ii = 0; ii < icnt; ii++) {
            const int i = i0 + ii;
            float2 s = bias;
            #pragma unroll
            for (int t = 0; t < 9; t++) {
                const float w = adjw[i*9+t];
                float2 v = h2f(*(unsigned*)(d1h + (g*64 + adji[i*9+t]) * DSH + cl2*2));
                s.x += w * v.x;
                s.y += w * v.y;
            }
            ps.x += fmaxf(s.x, 0.0f);
            ps.y += fmaxf(s.y, 0.0f);
        }
        ps.x += __shfl_xor_sync(0xFFFFFFFFu, ps.x, 1);
        ps.y += __shfl_xor_sync(0xFFFFFFFFu, ps.y, 1);
        ps.x += __shfl_xor_sync(0xFFFFFFFFu, ps.x, 2);
        ps.y += __shfl_xor_sync(0xFFFFFFFFu, ps.y, 2);
        if (quarter == 0) {
            pooled[g * C2 + cl2*2]     = ps.x * (1.0f / 49.0f);
            pooled[g * C2 + cl2*2 + 1] = ps.y * (1.0f / 49.0f);
        }
    }
    __syncthreads();

    if (tid < BT * NCLS) {
        const int g = tid / NCLS, o = tid - g * NCLS;
        float s = __ldg(&bf[o]);
        const float* pp = pooled + g * C2;
        #pragma unroll 8
        for (int k = 0; k < C2; k++) s += pp[k] * __ldg(&Wf[k * NCLS + o]);
        out[(size_t)(b0 + g) * NCLS + o] = s;
    }
}

extern "C" void kernel_launch(void* const* d_in, const int* in_sizes, int n_in,
                              void* d_out, int out_size)
{
    const float* x  = (const float*)d_in[0];
    const float* W1 = (const float*)d_in[1];
    const float* b1 = (const float*)d_in[2];
    const float* W2 = (const float*)d_in[3];
    const float* b2 = (const float*)d_in[4];
    const float* Wf = (const float*)d_in[5];
    const float* bf = (const float*)d_in[6];
    float* out = (float*)d_out;

    const int B = in_sizes[0] / (NNODE * DIM);   // 4096

    prep_weights<<<(C1 * DIM + C1 * C2 + 255) / 256, 256>>>(W1, W2);

    cudaFuncSetAttribute(gnn_fused, cudaFuncAttributeMaxDynamicSharedMemorySize, SMEM_BYTES);
    gnn_fused<<<B / BT, TPB, SMEM_BYTES>>>(x, b1, b2, Wf, bf, out);
}

// round 16
// speedup vs baseline: 2.7059x; 1.1028x over previous
#include <cuda_runtime.h>
#include <cuda_fp16.h>
#include <stdint.h>

#define TPB   512
#define NNODE 49
#define BT    2
#define DIM   768
#define C1    256
#define C2    128
#define NCLS  13
#define NST1  24           // 768/32 K32 stages
#define NST2  8            // 256/32

#define SROW 80            // stage tile row stride bytes -> conflict-free LDSM
#define SH   264           // H1 row stride (fp16 elems) = 528B
#define DSH  264           // d1h row stride (fp16 elems) = 528B (256 cols + pad)
#define SRA  272           // ADJ2 row stride bytes (128 fp16 + pad)

// ---- GEMM1 stage layout (bytes within stage) ----
#define A_T  0             // 128 x 80 (fp16)
#define B_T  10240         // 256 x 80 (fp16)
#define STG  30720         // x4 stages: [0, 122880)
// ---- phase-2 layout (aliases stage region; GEMM1 retired first) ----
#define OFF_H1   0         // 128 x 264 fp16 = 67584
#define OFF_D1S  67584     // 128 x 264 fp16 = 67584 -> 135168
#define OFF_B2   135168    // 4 stages x 10240 -> 176128
#define B2_STG   10240
// ---- persistent (no alias) ----
#define OFF_ADJ2 176128    // 128 x 272 B = 34816 -> 210944
#define OFF_DINV 210944    // 256
#define OFF_POOL 211200    // 2 x 128 fp32 = 1024
#define SMEM_BYTES 212224

// ---- pre-converted weights (filled by prep kernel) ----
__device__ __half g_W1[C1 * DIM];
__device__ __half g_W2[C2 * C1];

__device__ __forceinline__ void mma_f16(float* c, const unsigned* a, const unsigned* b) {
    asm volatile(
        "mma.sync.aligned.m16n8k16.row.col.f32.f16.f16.f32 "
        "{%0,%1,%2,%3}, {%4,%5,%6,%7}, {%8,%9}, {%0,%1,%2,%3};\n"
        : "+f"(c[0]), "+f"(c[1]), "+f"(c[2]), "+f"(c[3])
        : "r"(a[0]), "r"(a[1]), "r"(a[2]), "r"(a[3]), "r"(b[0]), "r"(b[1]));
}
__device__ __forceinline__ void ldsm4(unsigned* r, uint32_t addr) {
    asm volatile("ldmatrix.sync.aligned.m8n8.x4.shared.b16 {%0,%1,%2,%3}, [%4];"
        : "=r"(r[0]), "=r"(r[1]), "=r"(r[2]), "=r"(r[3]) : "r"(addr));
}
__device__ __forceinline__ void ldsm4t(unsigned* r, uint32_t addr) {
    asm volatile("ldmatrix.sync.aligned.m8n8.x4.trans.shared.b16 {%0,%1,%2,%3}, [%4];"
        : "=r"(r[0]), "=r"(r[1]), "=r"(r[2]), "=r"(r[3]) : "r"(addr));
}
__device__ __forceinline__ void cpa16(uint32_t dst, const void* src) {
    asm volatile("cp.async.cg.shared.global [%0], [%1], 16;" :: "r"(dst), "l"(src));
}
#define CPA_COMMIT() asm volatile("cp.async.commit_group;" ::: "memory")
#define CPA_WAIT0()  asm volatile("cp.async.wait_group 0;" ::: "memory")

__device__ __forceinline__ unsigned packh(__half a, __half b) {
    return ((unsigned)__half_as_ushort(b) << 16) | (unsigned)__half_as_ushort(a);
}
__device__ __forceinline__ unsigned packf(float a, float b) {
    return packh(__float2half(a), __float2half(b));
}

// ==================== prep: convert + transpose weights ====================
__global__ void prep_weights(const float* __restrict__ W1, const float* __restrict__ W2) {
    int idx = blockIdx.x * blockDim.x + threadIdx.x;
    if (idx < C1 * DIM) {                       // W1 [768][256] -> [256][768]
        int k = idx >> 8, n = idx & 255;
        g_W1[n * DIM + k] = __float2half(W1[idx]);
    } else if (idx < C1 * DIM + C1 * C2) {      // W2 [256][128] -> [128][256]
        int j = idx - C1 * DIM;
        int k = j >> 7, n = j & 127;
        g_W2[n * C1 + k] = __float2half(W2[j]);
    }
}

// =========================== main fused kernel ===========================
__global__ void __launch_bounds__(TPB, 1)
gnn_fused(const float* __restrict__ x,  const float* __restrict__ b1,
          const float* __restrict__ b2, const float* __restrict__ Wf,
          const float* __restrict__ bf, float* __restrict__ out)
{
    extern __shared__ unsigned char smem[];
    const uint32_t sbase = (uint32_t)__cvta_generic_to_shared(smem);

    float*  dinv   = (float*)(smem + OFF_DINV);
    float*  pooled = (float*)(smem + OFF_POOL);
    __half* d1h    = (__half*)(smem + OFF_D1S);
    __half* adj2   = (__half*)(smem + OFF_ADJ2);

    const int tid  = threadIdx.x;
    const int lane = tid & 31;
    const int wid  = tid >> 5;    // 0..15
    const int wm   = wid >> 2;    // 0..3  (m32 block)
    const int wn   = wid & 3;     // 0..3  (n64 G1 / n32 G2/ADJ)
    const int tr   = lane >> 2;
    const int tc   = lane & 3;
    const int b0   = blockIdx.x * BT;

    // ldmatrix lane patterns
    const int lrow  = (lane & 7) + ((lane >> 3) & 1) * 8;  // normal (A / B[n][k])
    const int lkb   = (lane >> 4) * 16;
    const int krowB = (lane & 7) + ((lane >> 4) & 1) * 8;  // trans (B from [k][n])
    const int nbB   = ((lane >> 3) & 1) * 16;

    // ---- dinv + pooled init ----
    if (tid < NNODE) {
        int r = tid / 7, c = tid % 7;
        int nr = min(r + 1, 6) - max(r - 1, 0) + 1;
        int nc = min(c + 1, 6) - max(c - 1, 0) + 1;
        dinv[tid] = 1.0f / sqrtf((float)(nr * nc));
    }
    if (tid < BT * C2) pooled[tid] = 0.0f;
    __syncthreads();
    // ---- build block-diagonal fp16 ADJ2 [128 x 128] ----
    for (int idx = tid; idx < 128 * 128; idx += TPB) {
        const int i = idx >> 7, j = idx & 127;
        float w = 0.0f;
        if ((i >> 6) == (j >> 6)) {
            const int ni = i & 63, nj = j & 63;
            if (ni < NNODE && nj < NNODE) {
                const int ri = ni / 7, ci = ni % 7, rj = nj / 7, cj = nj % 7;
                if (abs(ri - rj) <= 1 && abs(ci - cj) <= 1) w = dinv[ni] * dinv[nj];
            }
        }
        adj2[i * (SRA / 2) + j] = __float2half(w);
    }

    // ---- staging thread assignments (512 threads) ----
    const int arow  = tid >> 2;
    const int ac    = tid & 3;
    const int ag    = arow >> 6;
    const int anode = arow & 63;
    const bool aval = (anode < NNODE);
    const float* pxa = x + ((size_t)(b0 + ag) * NNODE + min(anode, NNODE - 1)) * DIM + ac * 8;
    const uint32_t adst = (uint32_t)(arow * SROW + ac * 16);
    const int bn  = tid >> 1;
    const int bc0 = (tid & 1) * 2;
    const __half* pw1 = g_W1 + (size_t)bn * DIM + bc0 * 8;
    const uint32_t bdst = (uint32_t)(B_T + bn * SROW + bc0 * 16);

    // frag base byte offsets
    const uint32_t aoff = (uint32_t)((wm * 32 + lrow) * SROW + lkb);
    const uint32_t boff = (uint32_t)((wn * 64 + lrow) * SROW + lkb);

    // ---- stage helpers ----
    auto ldA = [&](int kt, uint4& r) {
        if (aval) {
            float4 a = *(const float4*)(pxa + kt * 32);
            float4 b = *(const float4*)(pxa + kt * 32 + 4);
            r.x = packf(a.x, a.y); r.y = packf(a.z, a.w);
            r.z = packf(b.x, b.y); r.w = packf(b.z, b.w);
        } else r = make_uint4(0, 0, 0, 0);
    };
    auto stsA = [&](uint32_t stg, const uint4& v) {
        asm volatile("st.shared.v4.b32 [%0], {%1,%2,%3,%4};"
                     :: "r"(sbase + stg + A_T + adst),
                        "r"(v.x), "r"(v.y), "r"(v.z), "r"(v.w) : "memory");
    };
    auto fillB = [&](int kt, uint32_t stg) {
        const int ke = kt * 32;
        #pragma unroll
        for (int c = 0; c < 2; c++)
            cpa16(sbase + stg + bdst + c * 16, pw1 + ke + c * 8);
        CPA_COMMIT();
    };

    // ===== GEMM1: T1 = X @ W1  (128 x 256 x 768, fp16, pair-stage) =====
    float acc[16][4];
    #pragma unroll
    for (int j = 0; j < 16; j++)
        #pragma unroll
        for (int k = 0; k < 4; k++) acc[j][k] = 0.0f;

    auto compute1 = [&](int kt) {
        const uint32_t cs = (uint32_t)(kt & 3) * STG;
        #pragma unroll
        for (int kh = 0; kh < 2; kh++) {
            unsigned af[2][4];
            #pragma unroll
            for (int mi = 0; mi < 2; mi++)
                ldsm4(af[mi], sbase + cs + A_T + aoff + mi * 16 * SROW + kh * 32);
            #pragma unroll
            for (int p = 0; p < 4; p++) {
                unsigned bh4[4];
                ldsm4(bh4, sbase + cs + B_T + boff + p * 16 * SROW + kh * 32);
                #pragma unroll
                for (int h = 0; h < 2; h++) {
                    const int nj = p * 2 + h;
                    unsigned bh[2] = { bh4[h], bh4[2 + h] };
                    #pragma unroll
                    for (int mi = 0; mi < 2; mi++)
                        mma_f16(acc[mi*8+nj], af[mi], bh);
                }
            }
        }
    };

    uint4 rP0, rP1;
    {
        uint4 t0, t1;
        ldA(0, t0); ldA(1, t1);
        stsA(0, t0); stsA(STG, t1);
        fillB(0, 0); fillB(1, STG);
        ldA(2, rP0); ldA(3, rP1);
    }

    #pragma unroll 1
    for (int kt = 0; kt < NST1; kt += 2) {
        CPA_WAIT0();
        __syncthreads();
        if (kt + 2 < NST1) {
            const uint32_t n0 = (uint32_t)((kt + 2) & 3) * STG;
            const uint32_t n1 = (uint32_t)((kt + 3) & 3) * STG;
            stsA(n0, rP0); fillB(kt + 2, n0);
            stsA(n1, rP1); fillB(kt + 3, n1);
            if (kt + 4 < NST1) { ldA(kt + 4, rP0); ldA(kt + 5, rP1); }
        }
        compute1(kt);
        compute1(kt + 1);
    }
    __syncthreads();

    // GEMM2 B staging
    const int b2n = tid >> 2;
    const int b2c = tid & 3;
    const __half* pw2 = g_W2 + (size_t)b2n * C1 + b2c * 8;
    const uint32_t b2dst = (uint32_t)(b2n * SROW + b2c * 16);
    auto fill2 = [&](int kt) {
        cpa16(sbase + OFF_B2 + (uint32_t)(kt & 3) * B2_STG + b2dst, pw2 + kt * 32);
        CPA_COMMIT();
    };

    // ===== epilogue 1 (tensorized): store T1, ADJ-GEMM, bias+relu -> H1 =====
    __half* H1 = (__half*)(smem + OFF_H1);
    const int g2 = wm >> 1;
    {
        // store all acc -> d1h [node][256ch] (frees acc)
        #pragma unroll
        for (int mi = 0; mi < 2; mi++)
            #pragma unroll
            for (int nj = 0; nj < 8; nj++) {
                const int row = wm*32 + mi*16 + tr;
                const int col = wn*64 + nj*8 + tc*2;
                float* a = acc[mi*8+nj];
                *(unsigned*)(d1h + row * DSH + col)       = packf(a[0], a[1]);
                *(unsigned*)(d1h + (row + 8) * DSH + col) = packf(a[2], a[3]);
            }
        fill2(0); fill2(1);        // prefetch GEMM2 B stages 0,1
        __syncthreads();

        const uint32_t adjA = sbase + OFF_ADJ2 +
            (uint32_t)((wm*32 + lrow) * SRA + g2*128 + lkb);
        const uint32_t btB  = sbase + OFF_D1S +
            (uint32_t)((g2*64 + krowB) * (DSH*2) + nbB);

        #pragma unroll 1
        for (int ci = 0; ci < 2; ci++) {
            float e[8][4];
            #pragma unroll
            for (int j = 0; j < 8; j++)
                #pragma unroll
                for (int k = 0; k < 4; k++) e[j][k] = 0.0f;
            #pragma unroll
            for (int kt = 0; kt < 4; kt++) {
                unsigned aA[2][4];
                #pragma unroll
                for (int mi = 0; mi < 2; mi++)
                    ldsm4(aA[mi], adjA + mi*16*SRA + kt*32);
                #pragma unroll
                for (int p = 0; p < 2; p++) {
                    unsigned bt4[4];
                    ldsm4t(bt4, btB + kt*16*(DSH*2) + (uint32_t)(ci*128 + wn*32 + p*16)*2);
                    #pragma unroll
                    for (int h = 0; h < 2; h++) {
                        unsigned bh[2] = { bt4[h], bt4[2+h] };
                        #pragma unroll
                        for (int mi = 0; mi < 2; mi++)
                            mma_f16(e[mi*4 + p*2 + h], aA[mi], bh);
                    }
                }
            }
            // bias + relu -> H1
            #pragma unroll
            for (int mi = 0; mi < 2; mi++)
                #pragma unroll
                for (int nj = 0; nj < 4; nj++) {
                    const int row = wm*32 + mi*16 + tr;
                    const int col = ci*128 + wn*32 + nj*8 + tc*2;
                    float2 bb = __ldg((const float2*)(b1 + col));
                    float* v = e[mi*4+nj];
                    *(unsigned*)(H1 + row * SH + col) =
                        packf(fmaxf(v[0] + bb.x, 0.f), fmaxf(v[1] + bb.y, 0.f));
                    *(unsigned*)(H1 + (row + 8) * SH + col) =
                        packf(fmaxf(v[2] + bb.x, 0.f), fmaxf(v[3] + bb.y, 0.f));
                }
        }
        __syncthreads();
    }

    // ===== GEMM2: T2 = H1 @ W2  (128 x 128 x 256, fp16, pair-stage) =====
    float acc2[8][4];
    #pragma unroll
    for (int j = 0; j < 8; j++)
        #pragma unroll
        for (int k = 0; k < 4; k++) acc2[j][k] = 0.0f;

    const uint32_t hoff  = (uint32_t)((wm * 32 + lrow) * (SH * 2) + lkb);
    const uint32_t b2off = (uint32_t)((wn * 32 + lrow) * SROW + lkb);

    auto compute2 = [&](int kt) {
        const uint32_t cs = OFF_B2 + (uint32_t)(kt & 3) * B2_STG;
        #pragma unroll
        for (int kh = 0; kh < 2; kh++) {
            unsigned af[2][4];
            #pragma unroll
            for (int mi = 0; mi < 2; mi++)
                ldsm4(af[mi], sbase + OFF_H1 + hoff + mi*16*(SH*2) + kt*64 + kh*32);
            #pragma unroll
            for (int p = 0; p < 2; p++) {
                unsigned bh4[4];
                ldsm4(bh4, sbase + cs + b2off + p*16*SROW + kh*32);
                #pragma unroll
                for (int h = 0; h < 2; h++) {
                    const int nj = p*2 + h;
                    unsigned bh[2] = { bh4[h], bh4[2+h] };
                    #pragma unroll
                    for (int mi = 0; mi < 2; mi++)
                        mma_f16(acc2[mi*4+nj], af[mi], bh);
                }
            }
        }
    };

    #pragma unroll 1
    for (int kt = 0; kt < NST2; kt += 2) {
        CPA_WAIT0();
        __syncthreads();
        if (kt + 2 < NST2) { fill2(kt + 2); fill2(kt + 3); }
        compute2(kt);
        compute2(kt + 1);
    }
    __syncthreads();

    // ===== epilogue 2 (tensorized): store T2, ADJ-GEMM, masked relu-pool =====
    {
        #pragma unroll
        for (int mi = 0; mi < 2; mi++)
            #pragma unroll
            for (int nj = 0; nj < 4; nj++) {
                const int row = wm*32 + mi*16 + tr;
                const int col = wn*32 + nj*8 + tc*2;
                float* a = acc2[mi*4+nj];
                *(unsigned*)(d1h + row * DSH + col)       = packf(a[0], a[1]);
                *(unsigned*)(d1h + (row + 8) * DSH + col) = packf(a[2], a[3]);
            }
        __syncthreads();

        const uint32_t adjA = sbase + OFF_ADJ2 +
            (uint32_t)((wm*32 + lrow) * SRA + g2*128 + lkb);
        const uint32_t btB  = sbase + OFF_D1S +
            (uint32_t)((g2*64 + krowB) * (DSH*2) + nbB);

        float e[8][4];
        #pragma unroll
        for (int j = 0; j < 8; j++)
            #pragma unroll
            for (int k = 0; k < 4; k++) e[j][k] = 0.0f;
        #pragma unroll
        for (int kt = 0; kt < 4; kt++) {
            unsigned aA[2][4];
            #pragma unroll
            for (int mi = 0; mi < 2; mi++)
                ldsm4(aA[mi], adjA + mi*16*SRA + kt*32);
            #pragma unroll
            for (int p = 0; p < 2; p++) {
                unsigned bt4[4];
                ldsm4t(bt4, btB + kt*16*(DSH*2) + (uint32_t)(wn*32 + p*16)*2);
                #pragma unroll
                for (int h = 0; h < 2; h++) {
                    unsigned bh[2] = { bt4[h], bt4[2+h] };
                    #pragma unroll
                    for (int mi = 0; mi < 2; mi++)
                        mma_f16(e[mi*4 + p*2 + h], aA[mi], bh);
                }
            }
        }
        // masked bias+relu pool (sum over valid nodes), shfl-reduce over tr
        #pragma unroll
        for (int nj = 0; nj < 4; nj++) {
            const int col = wn*32 + nj*8 + tc*2;
            float2 bb = __ldg((const float2*)(b2 + col));
            float s0 = 0.0f, s1 = 0.0f;
            #pragma unroll
            for (int mi = 0; mi < 2; mi++) {
                const int r = wm*32 + mi*16 + tr;
                float* v = e[mi*4+nj];
                if ((r & 63) < NNODE) {
                    s0 += fmaxf(v[0] + bb.x, 0.f);
                    s1 += fmaxf(v[1] + bb.y, 0.f);
                }
                if (((r + 8) & 63) < NNODE) {
                    s0 += fmaxf(v[2] + bb.x, 0.f);
                    s1 += fmaxf(v[3] + bb.y, 0.f);
                }
            }
            s0 += __shfl_xor_sync(0xFFFFFFFFu, s0, 4);
            s1 += __shfl_xor_sync(0xFFFFFFFFu, s1, 4);
            s0 += __shfl_xor_sync(0xFFFFFFFFu, s0, 8);
            s1 += __shfl_xor_sync(0xFFFFFFFFu, s1, 8);
            s0 += __shfl_xor_sync(0xFFFFFFFFu, s0, 16);
            s1 += __shfl_xor_sync(0xFFFFFFFFu, s1, 16);
            if (tr == 0) {
                atomicAdd(&pooled[g2 * C2 + col], s0);
                atomicAdd(&pooled[g2 * C2 + col + 1], s1);
            }
        }
        __syncthreads();
    }

    if (tid < BT * NCLS) {
        const int g = tid / NCLS, o = tid - g * NCLS;
        float dot = 0.0f;
        const float* pp = pooled + g * C2;
        #pragma unroll 8
        for (int k = 0; k < C2; k++) dot += pp[k] * __ldg(&Wf[k * NCLS + o]);
        out[(size_t)(b0 + g) * NCLS + o] = __ldg(&bf[o]) + dot * (1.0f / 49.0f);
    }
}

extern "C" void kernel_launch(void* const* d_in, const int* in_sizes, int n_in,
                              void* d_out, int out_size)
{
    const float* x  = (const float*)d_in[0];
    const float* W1 = (const float*)d_in[1];
    const float* b1 = (const float*)d_in[2];
    const float* W2 = (const float*)d_in[3];
    const float* b2 = (const float*)d_in[4];
    const float* Wf = (const float*)d_in[5];
    const float* bf = (const float*)d_in[6];
    float* out = (float*)d_out;

    const int B = in_sizes[0] / (NNODE * DIM);   // 4096

    prep_weights<<<(C1 * DIM + C1 * C2 + 255) / 256, 256>>>(W1, W2);

    cudaFuncSetAttribute(gnn_fused, cudaFuncAttributeMaxDynamicSharedMemorySize, SMEM_BYTES);
    gnn_fused<<<B / BT, TPB, SMEM_BYTES>>>(x, b1, b2, Wf, bf, out);
}